// round 13
// baseline (speedup 1.0000x reference)
#include <cuda_runtime.h>
#include <cuda_bf16.h>
#include <math.h>
#include <stdint.h>

#define BATCH 2
#define SEQ   2048
#define DIM   1024
#define NHEAD 16
#define HD    64
#define MROWS (BATCH * SEQ)   // 4096
#define NQKV  (3 * DIM)       // 3072

// ---------------- scratch (device globals; no runtime allocation) ----------
__device__ __nv_bfloat16 g_xh[MROWS * DIM];
__device__ __nv_bfloat16 g_xl[MROWS * DIM];
__device__ __nv_bfloat16 g_wth[4 * DIM * DIM];
__device__ __nv_bfloat16 g_wtl[4 * DIM * DIM];
__device__ __nv_bfloat16 g_qkvh[MROWS * NQKV];
__device__ __nv_bfloat16 g_qkvl[MROWS * NQKV];

// ---------------- PTX helpers (sm_80-era only; no 'a'-gated features) ------
__device__ __forceinline__ uint32_t smem_u32(const void* p) {
    uint32_t a;
    asm("{ .reg .u64 t; cvta.to.shared.u64 t, %1; cvt.u32.u64 %0, t; }"
        : "=r"(a) : "l"(p));
    return a;
}
__device__ __forceinline__ void cp_async16(uint32_t saddr, const void* gptr) {
    asm volatile("cp.async.cg.shared.global [%0], [%1], 16;"
                 :: "r"(saddr), "l"(gptr));
}
__device__ __forceinline__ void cp_commit() {
    asm volatile("cp.async.commit_group;");
}
template <int N>
__device__ __forceinline__ void cp_wait() {
    asm volatile("cp.async.wait_group %0;" :: "n"(N));
}
__device__ __forceinline__ void ldsm4(uint32_t* r, uint32_t addr) {
    asm volatile("ldmatrix.sync.aligned.m8n8.x4.shared.b16 {%0,%1,%2,%3}, [%4];"
                 : "=r"(r[0]), "=r"(r[1]), "=r"(r[2]), "=r"(r[3]) : "r"(addr));
}
__device__ __forceinline__ void ldsm4t(uint32_t* r, uint32_t addr) {
    asm volatile("ldmatrix.sync.aligned.m8n8.x4.trans.shared.b16 {%0,%1,%2,%3}, [%4];"
                 : "=r"(r[0]), "=r"(r[1]), "=r"(r[2]), "=r"(r[3]) : "r"(addr));
}
__device__ __forceinline__ void mma16816(float* c, const uint32_t* a, const uint32_t* b) {
    asm volatile(
        "mma.sync.aligned.m16n8k16.row.col.f32.bf16.bf16.f32 "
        "{%0,%1,%2,%3}, {%4,%5,%6,%7}, {%8,%9}, {%0,%1,%2,%3};"
        : "+f"(c[0]), "+f"(c[1]), "+f"(c[2]), "+f"(c[3])
        : "r"(a[0]), "r"(a[1]), "r"(a[2]), "r"(a[3]), "r"(b[0]), "r"(b[1]));
}
__device__ __forceinline__ uint32_t pack_bf16(float a, float b) {
    __nv_bfloat162 t = __floats2bfloat162_rn(a, b);
    return *(uint32_t*)&t;
}
__device__ __forceinline__ void split_pack(float a, float b, uint32_t& hi, uint32_t& lo) {
    __nv_bfloat16 ah = __float2bfloat16_rn(a);
    __nv_bfloat16 bh = __float2bfloat16_rn(b);
    float al = a - __bfloat162float(ah);
    float bl = b - __bfloat162float(bh);
    __nv_bfloat162 th; th.x = ah; th.y = bh;
    hi = *(uint32_t*)&th;
    lo = pack_bf16(al, bl);
}

// ---------------- split / fused transpose-split kernels ---------------------
__global__ __launch_bounds__(256) void split_kernel(
    const float4* __restrict__ in, __nv_bfloat16* __restrict__ hi,
    __nv_bfloat16* __restrict__ lo, int n4)
{
    int i = blockIdx.x * blockDim.x + threadIdx.x;
    if (i >= n4) return;
    float4 v = in[i];
    float f[4] = {v.x, v.y, v.z, v.w};
    __nv_bfloat162 h2[2], l2[2];
    #pragma unroll
    for (int j = 0; j < 4; j++) {
        __nv_bfloat16 h = __float2bfloat16_rn(f[j]);
        __nv_bfloat16 l = __float2bfloat16_rn(f[j] - __bfloat162float(h));
        ((__nv_bfloat16*)h2)[j] = h;
        ((__nv_bfloat16*)l2)[j] = l;
    }
    ((__nv_bfloat162*)hi)[2 * i + 0] = h2[0];
    ((__nv_bfloat162*)hi)[2 * i + 1] = h2[1];
    ((__nv_bfloat162*)lo)[2 * i + 0] = l2[0];
    ((__nv_bfloat162*)lo)[2 * i + 1] = l2[1];
}

// all 4 weights: W[K,N] fp32 -> Th/Tl [N,K] bf16 ; blockIdx.z picks the weight
__global__ __launch_bounds__(256) void transpose_split4_kernel(
    const float* __restrict__ W0, const float* __restrict__ W1,
    const float* __restrict__ W2, const float* __restrict__ W3,
    __nv_bfloat16* __restrict__ Th, __nv_bfloat16* __restrict__ Tl)
{
    __shared__ float t[32][33];
    const int z = blockIdx.z;
    const float* W = (z == 0) ? W0 : (z == 1) ? W1 : (z == 2) ? W2 : W3;
    __nv_bfloat16* Tho = Th + (size_t)z * DIM * DIM;
    __nv_bfloat16* Tlo = Tl + (size_t)z * DIM * DIM;
    const int tx = threadIdx.x & 31, ty = threadIdx.x >> 5;
    const int bx = blockIdx.x * 32, by = blockIdx.y * 32;
    #pragma unroll
    for (int s = 0; s < 4; s++)
        t[ty + s * 8][tx] = W[(size_t)(by + ty + s * 8) * DIM + bx + tx];
    __syncthreads();
    #pragma unroll
    for (int s = 0; s < 4; s++) {
        float v = t[tx][ty + s * 8];
        __nv_bfloat16 h = __float2bfloat16_rn(v);
        __nv_bfloat16 l = __float2bfloat16_rn(v - __bfloat162float(h));
        size_t o = (size_t)(bx + ty + s * 8) * DIM + by + tx;
        Tho[o] = h; Tlo[o] = l;
    }
}

// ---------------- shared GEMM plumbing: 128x256 tile, K=64 chunks, 2 stages -
#define GS3   72                          // row stride (elems) = 144 B
#define AT3   (128 * GS3 * 2)             // 18432 B (A tile)
#define BT3   (256 * GS3 * 2)             // 36864 B (B tile)
#define GB3   (2 * AT3 + 2 * BT3)         // 110592 B per stage
#define GEMM_SMEM (2 * GB3)               // 221184 B (2 stages)
#define NCH3  (DIM / 64)                  // 16 chunks

#define ISSUE_CHUNK3(c, buf, bRowBase) { \
    const int ko_ = (c) * 64; \
    uint32_t s0 = sbase + (buf) * GB3; \
    _Pragma("unroll") \
    for (int i = 0; i < 4; i++) { \
        int idx = tid + i * 256; \
        int row = idx >> 3, seg = idx & 7; \
        uint32_t so = row * 144 + seg * 16; \
        cp_async16(s0 + so,       Ah + (size_t)(blockRow + row) * DIM + ko_ + seg * 8); \
        cp_async16(s0 + AT3 + so, Al + (size_t)(blockRow + row) * DIM + ko_ + seg * 8); \
    } \
    _Pragma("unroll") \
    for (int i = 0; i < 8; i++) { \
        int idx = tid + i * 256; \
        int row = idx >> 3, seg = idx & 7; \
        uint32_t so = row * 144 + seg * 16; \
        cp_async16(s0 + 2 * AT3 + so,       Bh + (size_t)((bRowBase) + row) * DIM + ko_ + seg * 8); \
        cp_async16(s0 + 2 * AT3 + BT3 + so, Bl + (size_t)((bRowBase) + row) * DIM + ko_ + seg * 8); \
    } }

#define GEMM_MAINLOOP() \
    ISSUE_CHUNK3(0, 0, blockCol); \
    cp_commit(); \
    for (int c = 0; c < NCH3; c++) { \
        if (c + 1 < NCH3) { ISSUE_CHUNK3(c + 1, (c + 1) & 1, blockCol); } \
        cp_commit(); \
        if (c + 1 < NCH3) cp_wait<1>(); else cp_wait<0>(); \
        __syncthreads(); \
        const uint32_t s0 = sbase + (c & 1) * GB3; \
        _Pragma("unroll") \
        for (int kk = 0; kk < 4; kk++) { \
            uint32_t ah[4][4], al[4][4], bhf[4][4], blf[4][4]; \
            _Pragma("unroll") \
            for (int mi = 0; mi < 4; mi++) { \
                uint32_t ao = ((aRow + mi * 16) * GS3 + kk * 16 + aCol) * 2; \
                ldsm4(ah[mi], s0 + ao); \
                ldsm4(al[mi], s0 + AT3 + ao); \
            } \
            _Pragma("unroll") \
            for (int g = 0; g < 4; g++) { \
                uint32_t bo = ((bRow + g * 16) * GS3 + kk * 16 + bCol) * 2; \
                ldsm4(bhf[g], s0 + 2 * AT3 + bo); \
                ldsm4(blf[g], s0 + 2 * AT3 + BT3 + bo); \
            } \
            _Pragma("unroll") \
            for (int mi = 0; mi < 4; mi++) \
                _Pragma("unroll") \
                for (int ni = 0; ni < 8; ni++) { \
                    mma16816(acc[mi][ni], ah[mi], &bhf[ni >> 1][(ni & 1) * 2]); \
                    mma16816(acc[mi][ni], ah[mi], &blf[ni >> 1][(ni & 1) * 2]); \
                    mma16816(acc[mi][ni], al[mi], &bhf[ni >> 1][(ni & 1) * 2]); \
                } \
        } \
        __syncthreads(); \
    }

// ---------------- fused QKV GEMM: writes bf16 hi/lo, Q scaled by 0.125 -----
__global__ __launch_bounds__(256, 1)
void gemm_qkv_kernel(const __nv_bfloat16* __restrict__ Ah,
                     const __nv_bfloat16* __restrict__ Al,
                     const __nv_bfloat16* __restrict__ Bh,
                     const __nv_bfloat16* __restrict__ Bl,
                     const float* __restrict__ bq,
                     const float* __restrict__ bk,
                     const float* __restrict__ bv,
                     __nv_bfloat16* __restrict__ Ch,
                     __nv_bfloat16* __restrict__ Cl)
{
    extern __shared__ char smem[];
    const uint32_t sbase = smem_u32(smem);
    const int tid  = threadIdx.x;
    const int wid  = tid >> 5;
    const int lane = tid & 31;
    const int blockRow = blockIdx.y * 128;
    const int blockCol = blockIdx.x * 256;      // within one of Q/K/V
    const int wrow = (wid >> 2) * 64;
    const int wcol = (wid & 3) * 64;

    const float scale = (blockCol < DIM) ? 0.125f : 1.0f;
    const float* bsel;
    int cb;
    if (blockCol < DIM)            { bsel = bq; cb = blockCol; }
    else if (blockCol < 2 * DIM)   { bsel = bk; cb = blockCol - DIM; }
    else                           { bsel = bv; cb = blockCol - 2 * DIM; }

    float acc[4][8][4];
    #pragma unroll
    for (int mi = 0; mi < 4; mi++)
        #pragma unroll
        for (int ni = 0; ni < 8; ni++)
            #pragma unroll
            for (int j = 0; j < 4; j++) acc[mi][ni][j] = 0.f;

    const int aRow = wrow + (lane & 15);
    const int aCol = (lane >> 4) * 8;
    const int bRow = wcol + (lane >> 4) * 8 + (lane & 7);
    const int bCol = ((lane >> 3) & 1) * 8;

    GEMM_MAINLOOP();

    #pragma unroll
    for (int mi = 0; mi < 4; mi++) {
        const int r0 = blockRow + wrow + mi * 16 + (lane >> 2);
        #pragma unroll
        for (int ni = 0; ni < 8; ni++) {
            const int cc = wcol + ni * 8 + 2 * (lane & 3);
            float2 bv2 = *(const float2*)(bsel + cb + cc);
            const int gc = blockCol + cc;
            float v0x = (acc[mi][ni][0] + bv2.x) * scale;
            float v0y = (acc[mi][ni][1] + bv2.y) * scale;
            float v1x = (acc[mi][ni][2] + bv2.x) * scale;
            float v1y = (acc[mi][ni][3] + bv2.y) * scale;
            uint32_t h0, l0, h1, l1;
            split_pack(v0x, v0y, h0, l0);
            split_pack(v1x, v1y, h1, l1);
            *(uint32_t*)(Ch + (size_t)r0 * NQKV + gc)       = h0;
            *(uint32_t*)(Cl + (size_t)r0 * NQKV + gc)       = l0;
            *(uint32_t*)(Ch + (size_t)(r0 + 8) * NQKV + gc) = h1;
            *(uint32_t*)(Cl + (size_t)(r0 + 8) * NQKV + gc) = l1;
        }
    }
}

// ---------------- O-projection GEMM: fp32 out + bias -----------------------
__global__ __launch_bounds__(256, 1)
void gemm_mma_kernel(const __nv_bfloat16* __restrict__ Ah,
                     const __nv_bfloat16* __restrict__ Al,
                     const __nv_bfloat16* __restrict__ Bh,
                     const __nv_bfloat16* __restrict__ Bl,
                     const float* __restrict__ bias, float* __restrict__ C)
{
    extern __shared__ char smem[];
    const uint32_t sbase = smem_u32(smem);
    const int tid  = threadIdx.x;
    const int wid  = tid >> 5;
    const int lane = tid & 31;
    const int blockRow = blockIdx.y * 128;
    const int blockCol = blockIdx.x * 256;
    const int wrow = (wid >> 2) * 64;
    const int wcol = (wid & 3) * 64;

    float acc[4][8][4];
    #pragma unroll
    for (int mi = 0; mi < 4; mi++)
        #pragma unroll
        for (int ni = 0; ni < 8; ni++)
            #pragma unroll
            for (int j = 0; j < 4; j++) acc[mi][ni][j] = 0.f;

    const int aRow = wrow + (lane & 15);
    const int aCol = (lane >> 4) * 8;
    const int bRow = wcol + (lane >> 4) * 8 + (lane & 7);
    const int bCol = ((lane >> 3) & 1) * 8;

    GEMM_MAINLOOP();

    #pragma unroll
    for (int mi = 0; mi < 4; mi++) {
        const int r0 = blockRow + wrow + mi * 16 + (lane >> 2);
        #pragma unroll
        for (int ni = 0; ni < 8; ni++) {
            const int c0 = blockCol + wcol + ni * 8 + 2 * (lane & 3);
            float2 bv = *(const float2*)(bias + c0);
            float2 v0 = { acc[mi][ni][0] + bv.x, acc[mi][ni][1] + bv.y };
            float2 v1 = { acc[mi][ni][2] + bv.x, acc[mi][ni][3] + bv.y };
            *(float2*)(C + (size_t)r0 * DIM + c0)       = v0;
            *(float2*)(C + (size_t)(r0 + 8) * DIM + c0) = v1;
        }
    }
}

// ---------------- Flash attention (bf16-split mma, causal, softmax-one) ----
// Exact online-max softmax-one (required: the +1 in the denominator makes
// softmax-one non-shift-invariant, so M must be the true row max).
// One q-tile per CTA, largest-first (qt = 15 - bx) so HW work-steals the
// small diagonal CTAs into tail gaps.
#define FQS 72
#define FQ_ELE   (128 * FQS)
#define FKV_ELE  (64 * FQS)
#define FKVBUF   (4 * FKV_ELE)
#define FLASH_SMEM ((2 * FQ_ELE + 2 * FKVBUF) * 2)   // 110592 bytes

__global__ __launch_bounds__(128, 2) void flash_mma_kernel(
    const __nv_bfloat16* __restrict__ QKVh,
    const __nv_bfloat16* __restrict__ QKVl,
    __nv_bfloat16* __restrict__ Ch,
    __nv_bfloat16* __restrict__ Cl)
{
    const int qt   = 15 - blockIdx.x;     // 15..0 (largest workload first)
    const int bh   = blockIdx.y;          // 0..31
    const int b    = bh >> 4;
    const int h    = bh & 15;
    const int tid  = threadIdx.x;
    const int wid  = tid >> 5;
    const int lane = tid & 31;
    const int wrow = wid * 32;
    const size_t rowbase = (size_t)b * SEQ;
    const int qcol = h * HD;
    const int kcol = qcol + DIM;
    const int vcol = qcol + 2 * DIM;
    const int qbase = qt * 128;

    extern __shared__ __nv_bfloat16 fsm[];
    const uint32_t uQh = smem_u32(fsm);
    const uint32_t uQl = uQh + FQ_ELE * 2;
    const uint32_t uKV0 = uQl + FQ_ELE * 2;
    #define KV_KH(bb) (uKV0 + (bb) * FKVBUF * 2)
    #define KV_KL(bb) (KV_KH(bb) + FKV_ELE * 2)
    #define KV_VH(bb) (KV_KH(bb) + 2 * FKV_ELE * 2)
    #define KV_VL(bb) (KV_KH(bb) + 3 * FKV_ELE * 2)

    #define ISSUE_Q(qb) { \
        _Pragma("unroll") \
        for (int i = 0; i < 8; i++) { \
            int idx = tid + i * 128; \
            int r = idx >> 3, seg = idx & 7; \
            size_t g = (rowbase + (qb) + r) * NQKV + qcol + seg * 8; \
            cp_async16(uQh + r * 144 + seg * 16, QKVh + g); \
            cp_async16(uQl + r * 144 + seg * 16, QKVl + g); \
        } }

    #define ISSUE_KV(kb, bb) { \
        _Pragma("unroll") \
        for (int i = 0; i < 4; i++) { \
            int idx = tid + i * 128; \
            int r = idx >> 3, seg = idx & 7; \
            size_t gk = (rowbase + (kb) + r) * NQKV + kcol + seg * 8; \
            size_t gv = (rowbase + (kb) + r) * NQKV + vcol + seg * 8; \
            uint32_t so = r * 144 + seg * 16; \
            cp_async16(KV_KH(bb) + so, QKVh + gk); \
            cp_async16(KV_KL(bb) + so, QKVl + gk); \
            cp_async16(KV_VH(bb) + so, QKVh + gv); \
            cp_async16(KV_VL(bb) + so, QKVl + gv); \
        } }

    float sa[2][8][4];
    float oa[2][8][4];
    float m[4], l[4];
    #pragma unroll
    for (int mi = 0; mi < 2; mi++)
        #pragma unroll
        for (int ni = 0; ni < 8; ni++)
            #pragma unroll
            for (int j = 0; j < 4; j++) oa[mi][ni][j] = 0.f;
    #pragma unroll
    for (int i = 0; i < 4; i++) { m[i] = -INFINITY; l[i] = 0.f; }

    ISSUE_Q(qbase);
    ISSUE_KV(0, 0);
    cp_commit();

    const int nkt = 2 * qt + 2;
    for (int kt = 0; kt < nkt; kt++) {
        const int kbase = kt * 64;
        if (kt + 1 < nkt) { ISSUE_KV((kt + 1) * 64, (kt + 1) & 1); }
        cp_commit();
        if (kt + 1 < nkt) cp_wait<1>(); else cp_wait<0>();
        __syncthreads();

        const int bb = kt & 1;
        const uint32_t uKh = KV_KH(bb), uKl = KV_KL(bb);
        const uint32_t uVh = KV_VH(bb), uVl = KV_VL(bb);

        #pragma unroll
        for (int mi = 0; mi < 2; mi++)
            #pragma unroll
            for (int ni = 0; ni < 8; ni++)
                #pragma unroll
                for (int j = 0; j < 4; j++) sa[mi][ni][j] = 0.f;

        // ---- S = Q @ K^T (3-product split) ----
        #pragma unroll
        for (int kk = 0; kk < 4; kk++) {
            uint32_t aqh[2][4], aql[2][4];
            #pragma unroll
            for (int mi = 0; mi < 2; mi++) {
                uint32_t ao = ((wrow + mi * 16 + (lane & 15)) * FQS +
                               kk * 16 + (lane >> 4) * 8) * 2;
                ldsm4(aqh[mi], uQh + ao);
                ldsm4(aql[mi], uQl + ao);
            }
            #pragma unroll
            for (int g = 0; g < 4; g++) {
                uint32_t bh_[4], bl_[4];
                uint32_t bo = ((g * 16 + (lane >> 4) * 8 + (lane & 7)) * FQS +
                               kk * 16 + ((lane >> 3) & 1) * 8) * 2;
                ldsm4(bh_, uKh + bo);
                ldsm4(bl_, uKl + bo);
                #pragma unroll
                for (int mi = 0; mi < 2; mi++)
                    #pragma unroll
                    for (int p = 0; p < 2; p++) {
                        int ni = g * 2 + p;
                        mma16816(sa[mi][ni], aqh[mi], &bh_[p * 2]);
                        mma16816(sa[mi][ni], aqh[mi], &bl_[p * 2]);
                        mma16816(sa[mi][ni], aql[mi], &bh_[p * 2]);
                    }
            }
        }

        // ---- causal mask (near-diagonal tiles only) ----
        if (kbase + 63 > qbase + wrow) {
            #pragma unroll
            for (int mi = 0; mi < 2; mi++)
                #pragma unroll
                for (int ni = 0; ni < 8; ni++)
                    #pragma unroll
                    for (int j = 0; j < 4; j++) {
                        int qrow = qbase + wrow + mi * 16 + (lane >> 2) + (j >> 1) * 8;
                        int kc = kbase + ni * 8 + 2 * (lane & 3) + (j & 1);
                        if (kc > qrow) sa[mi][ni][j] = -INFINITY;
                    }
        }

        // ---- online softmax-one update (exact row max) ----
        #pragma unroll
        for (int mi = 0; mi < 2; mi++)
            #pragma unroll
            for (int rh = 0; rh < 2; rh++) {
                const int ri = mi * 2 + rh;
                float rmax = -INFINITY;
                #pragma unroll
                for (int ni = 0; ni < 8; ni++)
                    rmax = fmaxf(rmax, fmaxf(sa[mi][ni][rh * 2], sa[mi][ni][rh * 2 + 1]));
                rmax = fmaxf(rmax, __shfl_xor_sync(0xffffffffu, rmax, 1));
                rmax = fmaxf(rmax, __shfl_xor_sync(0xffffffffu, rmax, 2));
                float mnew = fmaxf(m[ri], rmax);
                float corr = __expf(m[ri] - mnew);
                float sum = 0.f;
                #pragma unroll
                for (int ni = 0; ni < 8; ni++)
                    #pragma unroll
                    for (int j2 = 0; j2 < 2; j2++) {
                        float p = __expf(sa[mi][ni][rh * 2 + j2] - mnew);
                        sa[mi][ni][rh * 2 + j2] = p;
                        sum += p;
                    }
                sum += __shfl_xor_sync(0xffffffffu, sum, 1);
                sum += __shfl_xor_sync(0xffffffffu, sum, 2);
                l[ri] = l[ri] * corr + sum;
                m[ri] = mnew;
                #pragma unroll
                for (int ni = 0; ni < 8; ni++)
                    #pragma unroll
                    for (int j2 = 0; j2 < 2; j2++)
                        oa[mi][ni][rh * 2 + j2] *= corr;
            }

        // ---- O += P @ V : V row-major, B-fragments via ldmatrix.trans ----
        #pragma unroll
        for (int kk = 0; kk < 4; kk++) {
            uint32_t ph[2][4], pl[2][4];
            #pragma unroll
            for (int mi = 0; mi < 2; mi++) {
                split_pack(sa[mi][2 * kk][0],     sa[mi][2 * kk][1],     ph[mi][0], pl[mi][0]);
                split_pack(sa[mi][2 * kk][2],     sa[mi][2 * kk][3],     ph[mi][1], pl[mi][1]);
                split_pack(sa[mi][2 * kk + 1][0], sa[mi][2 * kk + 1][1], ph[mi][2], pl[mi][2]);
                split_pack(sa[mi][2 * kk + 1][2], sa[mi][2 * kk + 1][3], ph[mi][3], pl[mi][3]);
            }
            #pragma unroll
            for (int dg = 0; dg < 4; dg++) {
                uint32_t bvh[4], bvl[4];
                uint32_t bo = ((kk * 16 + ((lane >> 3) & 1) * 8 + (lane & 7)) * FQS +
                               dg * 16 + (lane >> 4) * 8) * 2;
                ldsm4t(bvh, uVh + bo);
                ldsm4t(bvl, uVl + bo);
                #pragma unroll
                for (int mi = 0; mi < 2; mi++)
                    #pragma unroll
                    for (int p = 0; p < 2; p++) {
                        int ni = dg * 2 + p;
                        mma16816(oa[mi][ni], ph[mi], &bvh[p * 2]);
                        mma16816(oa[mi][ni], ph[mi], &bvl[p * 2]);
                        mma16816(oa[mi][ni], pl[mi], &bvh[p * 2]);
                    }
            }
        }
        __syncthreads();
    }

    // ---- epilogue: divide by (1 + l), write ctx bf16 hi/lo ----
    #pragma unroll
    for (int mi = 0; mi < 2; mi++) {
        const float inv0 = 1.f / (1.f + l[mi * 2 + 0]);
        const float inv1 = 1.f / (1.f + l[mi * 2 + 1]);
        const int r0 = qbase + wrow + mi * 16 + (lane >> 2);
        #pragma unroll
        for (int ni = 0; ni < 8; ni++) {
            const int c0 = ni * 8 + 2 * (lane & 3);
            uint32_t h0, l0, h1, l1;
            split_pack(oa[mi][ni][0] * inv0, oa[mi][ni][1] * inv0, h0, l0);
            split_pack(oa[mi][ni][2] * inv1, oa[mi][ni][3] * inv1, h1, l1);
            size_t o0 = (rowbase + r0) * DIM + qcol + c0;
            size_t o1 = (rowbase + r0 + 8) * DIM + qcol + c0;
            *(uint32_t*)(Ch + o0) = h0;
            *(uint32_t*)(Cl + o0) = l0;
            *(uint32_t*)(Ch + o1) = h1;
            *(uint32_t*)(Cl + o1) = l1;
        }
    }
}

// ---------------- launcher -------------------------------------------------
extern "C" void kernel_launch(void* const* d_in, const int* in_sizes, int n_in,
                              void* d_out, int out_size)
{
    const float* x  = (const float*)d_in[0];
    const float* Wq = (const float*)d_in[1];
    const float* bq = (const float*)d_in[2];
    const float* Wk = (const float*)d_in[3];
    const float* bk = (const float*)d_in[4];
    const float* Wv = (const float*)d_in[5];
    const float* bv = (const float*)d_in[6];
    const float* Wo = (const float*)d_in[7];
    const float* bo = (const float*)d_in[8];
    float* out = (float*)d_out;

    __nv_bfloat16 *xh, *xl, *wth, *wtl, *qkvh, *qkvl;
    cudaGetSymbolAddress((void**)&xh,   g_xh);
    cudaGetSymbolAddress((void**)&xl,   g_xl);
    cudaGetSymbolAddress((void**)&wth,  g_wth);
    cudaGetSymbolAddress((void**)&wtl,  g_wtl);
    cudaGetSymbolAddress((void**)&qkvh, g_qkvh);
    cudaGetSymbolAddress((void**)&qkvl, g_qkvl);

    cudaFuncSetAttribute(flash_mma_kernel,
                         cudaFuncAttributeMaxDynamicSharedMemorySize, FLASH_SMEM);
    cudaFuncSetAttribute(gemm_qkv_kernel,
                         cudaFuncAttributeMaxDynamicSharedMemorySize, GEMM_SMEM);
    cudaFuncSetAttribute(gemm_mma_kernel,
                         cudaFuncAttributeMaxDynamicSharedMemorySize, GEMM_SMEM);

    const int n4 = MROWS * DIM / 4;

    split_kernel<<<(n4 + 255) / 256, 256>>>((const float4*)x, xh, xl, n4);
    dim3 tg(32, 32, 4);
    transpose_split4_kernel<<<tg, 256>>>(Wq, Wk, Wv, Wo, wth, wtl);

    dim3 gqkv(NQKV / 256, MROWS / 128);        // (12, 32)
    gemm_qkv_kernel<<<gqkv, 256, GEMM_SMEM>>>(xh, xl, wth, wtl, bq, bk, bv, qkvh, qkvl);

    dim3 attnGrid(16, BATCH * NHEAD);          // (16, 32): one q-tile per CTA
    flash_mma_kernel<<<attnGrid, 128, FLASH_SMEM>>>(qkvh, qkvl, xh, xl);

    dim3 go(DIM / 256, MROWS / 128);           // (4, 32)
    gemm_mma_kernel<<<go, 256, GEMM_SMEM>>>(xh, xl, wth + 3 * DIM * DIM, wtl + 3 * DIM * DIM, bo, out);
}

// round 15
// speedup vs baseline: 1.0505x; 1.0505x over previous
#include <cuda_runtime.h>
#include <cuda_bf16.h>
#include <math.h>
#include <stdint.h>

#define BATCH 2
#define SEQ   2048
#define DIM   1024
#define NHEAD 16
#define HD    64
#define MROWS (BATCH * SEQ)   // 4096
#define NQKV  (3 * DIM)       // 3072

// ---------------- scratch (device globals; no runtime allocation) ----------
__device__ __nv_bfloat16 g_xh[MROWS * DIM];
__device__ __nv_bfloat16 g_xl[MROWS * DIM];
__device__ __nv_bfloat16 g_wth[4 * DIM * DIM];
__device__ __nv_bfloat16 g_wtl[4 * DIM * DIM];
__device__ __nv_bfloat16 g_qkvh[MROWS * NQKV];
__device__ __nv_bfloat16 g_qkvl[MROWS * NQKV];

// ---------------- PTX helpers (sm_80-era only; no 'a'-gated features) ------
__device__ __forceinline__ uint32_t smem_u32(const void* p) {
    uint32_t a;
    asm("{ .reg .u64 t; cvta.to.shared.u64 t, %1; cvt.u32.u64 %0, t; }"
        : "=r"(a) : "l"(p));
    return a;
}
__device__ __forceinline__ void cp_async16(uint32_t saddr, const void* gptr) {
    asm volatile("cp.async.cg.shared.global [%0], [%1], 16;"
                 :: "r"(saddr), "l"(gptr));
}
__device__ __forceinline__ void cp_commit() {
    asm volatile("cp.async.commit_group;");
}
template <int N>
__device__ __forceinline__ void cp_wait() {
    asm volatile("cp.async.wait_group %0;" :: "n"(N));
}
__device__ __forceinline__ void ldsm4(uint32_t* r, uint32_t addr) {
    asm volatile("ldmatrix.sync.aligned.m8n8.x4.shared.b16 {%0,%1,%2,%3}, [%4];"
                 : "=r"(r[0]), "=r"(r[1]), "=r"(r[2]), "=r"(r[3]) : "r"(addr));
}
__device__ __forceinline__ void ldsm4t(uint32_t* r, uint32_t addr) {
    asm volatile("ldmatrix.sync.aligned.m8n8.x4.trans.shared.b16 {%0,%1,%2,%3}, [%4];"
                 : "=r"(r[0]), "=r"(r[1]), "=r"(r[2]), "=r"(r[3]) : "r"(addr));
}
__device__ __forceinline__ void mma16816(float* c, const uint32_t* a, const uint32_t* b) {
    asm volatile(
        "mma.sync.aligned.m16n8k16.row.col.f32.bf16.bf16.f32 "
        "{%0,%1,%2,%3}, {%4,%5,%6,%7}, {%8,%9}, {%0,%1,%2,%3};"
        : "+f"(c[0]), "+f"(c[1]), "+f"(c[2]), "+f"(c[3])
        : "r"(a[0]), "r"(a[1]), "r"(a[2]), "r"(a[3]), "r"(b[0]), "r"(b[1]));
}
__device__ __forceinline__ uint32_t pack_bf16(float a, float b) {
    __nv_bfloat162 t = __floats2bfloat162_rn(a, b);
    return *(uint32_t*)&t;
}
__device__ __forceinline__ void split_pack(float a, float b, uint32_t& hi, uint32_t& lo) {
    __nv_bfloat16 ah = __float2bfloat16_rn(a);
    __nv_bfloat16 bh = __float2bfloat16_rn(b);
    float al = a - __bfloat162float(ah);
    float bl = b - __bfloat162float(bh);
    __nv_bfloat162 th; th.x = ah; th.y = bh;
    hi = *(uint32_t*)&th;
    lo = pack_bf16(al, bl);
}

// ---------------- fused prep: weights transpose-split (z<4) + x split (z=4) -
__global__ __launch_bounds__(256) void prep_kernel(
    const float* __restrict__ x,
    const float* __restrict__ W0, const float* __restrict__ W1,
    const float* __restrict__ W2, const float* __restrict__ W3,
    __nv_bfloat16* __restrict__ Th, __nv_bfloat16* __restrict__ Tl,
    __nv_bfloat16* __restrict__ Xh, __nv_bfloat16* __restrict__ Xl)
{
    const int z = blockIdx.z;
    if (z == 4) {
        // x split: 1M float4 over 1024 (bx,by) blocks x 256 threads x 4 elems
        const int blockLin = blockIdx.y * 32 + blockIdx.x;
        const float4* in = (const float4*)x;
        #pragma unroll
        for (int s = 0; s < 4; s++) {
            int i = blockLin * 1024 + threadIdx.x + s * 256;
            float4 v = in[i];
            float f[4] = {v.x, v.y, v.z, v.w};
            __nv_bfloat162 h2[2], l2[2];
            #pragma unroll
            for (int j = 0; j < 4; j++) {
                __nv_bfloat16 h = __float2bfloat16_rn(f[j]);
                __nv_bfloat16 l = __float2bfloat16_rn(f[j] - __bfloat162float(h));
                ((__nv_bfloat16*)h2)[j] = h;
                ((__nv_bfloat16*)l2)[j] = l;
            }
            ((__nv_bfloat162*)Xh)[2 * i + 0] = h2[0];
            ((__nv_bfloat162*)Xh)[2 * i + 1] = h2[1];
            ((__nv_bfloat162*)Xl)[2 * i + 0] = l2[0];
            ((__nv_bfloat162*)Xl)[2 * i + 1] = l2[1];
        }
        return;
    }
    __shared__ float t[32][33];
    const float* W = (z == 0) ? W0 : (z == 1) ? W1 : (z == 2) ? W2 : W3;
    __nv_bfloat16* Tho = Th + (size_t)z * DIM * DIM;
    __nv_bfloat16* Tlo = Tl + (size_t)z * DIM * DIM;
    const int tx = threadIdx.x & 31, ty = threadIdx.x >> 5;
    const int bx = blockIdx.x * 32, by = blockIdx.y * 32;
    #pragma unroll
    for (int s = 0; s < 4; s++)
        t[ty + s * 8][tx] = W[(size_t)(by + ty + s * 8) * DIM + bx + tx];
    __syncthreads();
    #pragma unroll
    for (int s = 0; s < 4; s++) {
        float v = t[tx][ty + s * 8];
        __nv_bfloat16 h = __float2bfloat16_rn(v);
        __nv_bfloat16 l = __float2bfloat16_rn(v - __bfloat162float(h));
        size_t o = (size_t)(bx + ty + s * 8) * DIM + by + tx;
        Tho[o] = h; Tlo[o] = l;
    }
}

// ---------------- ctx split (after flash writes ctx as bf16 direct) --------
// (not needed: flash writes bf16 hi/lo directly)

// ---------------- shared GEMM plumbing: 128x256 tile, K=64 chunks, 2 stages -
#define GS3   72                          // row stride (elems) = 144 B
#define AT3   (128 * GS3 * 2)             // 18432 B (A tile)
#define BT3   (256 * GS3 * 2)             // 36864 B (B tile)
#define GB3   (2 * AT3 + 2 * BT3)         // 110592 B per stage
#define GEMM_SMEM (2 * GB3)               // 221184 B (2 stages)
#define NCH3  (DIM / 64)                  // 16 chunks

#define ISSUE_CHUNK3(c, buf, bRowBase) { \
    const int ko_ = (c) * 64; \
    uint32_t s0 = sbase + (buf) * GB3; \
    _Pragma("unroll") \
    for (int i = 0; i < 4; i++) { \
        int idx = tid + i * 256; \
        int row = idx >> 3, seg = idx & 7; \
        uint32_t so = row * 144 + seg * 16; \
        cp_async16(s0 + so,       Ah + (size_t)(blockRow + row) * DIM + ko_ + seg * 8); \
        cp_async16(s0 + AT3 + so, Al + (size_t)(blockRow + row) * DIM + ko_ + seg * 8); \
    } \
    _Pragma("unroll") \
    for (int i = 0; i < 8; i++) { \
        int idx = tid + i * 256; \
        int row = idx >> 3, seg = idx & 7; \
        uint32_t so = row * 144 + seg * 16; \
        cp_async16(s0 + 2 * AT3 + so,       Bh + (size_t)((bRowBase) + row) * DIM + ko_ + seg * 8); \
        cp_async16(s0 + 2 * AT3 + BT3 + so, Bl + (size_t)((bRowBase) + row) * DIM + ko_ + seg * 8); \
    } }

#define GEMM_MAINLOOP() \
    ISSUE_CHUNK3(0, 0, blockCol); \
    cp_commit(); \
    for (int c = 0; c < NCH3; c++) { \
        if (c + 1 < NCH3) { ISSUE_CHUNK3(c + 1, (c + 1) & 1, blockCol); } \
        cp_commit(); \
        if (c + 1 < NCH3) cp_wait<1>(); else cp_wait<0>(); \
        __syncthreads(); \
        const uint32_t s0 = sbase + (c & 1) * GB3; \
        _Pragma("unroll") \
        for (int kk = 0; kk < 4; kk++) { \
            uint32_t ah[4][4], al[4][4], bhf[4][4], blf[4][4]; \
            _Pragma("unroll") \
            for (int mi = 0; mi < 4; mi++) { \
                uint32_t ao = ((aRow + mi * 16) * GS3 + kk * 16 + aCol) * 2; \
                ldsm4(ah[mi], s0 + ao); \
                ldsm4(al[mi], s0 + AT3 + ao); \
            } \
            _Pragma("unroll") \
            for (int g = 0; g < 4; g++) { \
                uint32_t bo = ((bRow + g * 16) * GS3 + kk * 16 + bCol) * 2; \
                ldsm4(bhf[g], s0 + 2 * AT3 + bo); \
                ldsm4(blf[g], s0 + 2 * AT3 + BT3 + bo); \
            } \
            _Pragma("unroll") \
            for (int mi = 0; mi < 4; mi++) \
                _Pragma("unroll") \
                for (int ni = 0; ni < 8; ni++) { \
                    mma16816(acc[mi][ni], ah[mi], &bhf[ni >> 1][(ni & 1) * 2]); \
                    mma16816(acc[mi][ni], ah[mi], &blf[ni >> 1][(ni & 1) * 2]); \
                    mma16816(acc[mi][ni], al[mi], &bhf[ni >> 1][(ni & 1) * 2]); \
                } \
        } \
        __syncthreads(); \
    }

// ---------------- fused QKV GEMM: writes bf16 hi/lo, Q scaled by 0.125 -----
__global__ __launch_bounds__(256, 1)
void gemm_qkv_kernel(const __nv_bfloat16* __restrict__ Ah,
                     const __nv_bfloat16* __restrict__ Al,
                     const __nv_bfloat16* __restrict__ Bh,
                     const __nv_bfloat16* __restrict__ Bl,
                     const float* __restrict__ bq,
                     const float* __restrict__ bk,
                     const float* __restrict__ bv,
                     __nv_bfloat16* __restrict__ Ch,
                     __nv_bfloat16* __restrict__ Cl)
{
    extern __shared__ char smem[];
    const uint32_t sbase = smem_u32(smem);
    const int tid  = threadIdx.x;
    const int wid  = tid >> 5;
    const int lane = tid & 31;
    const int blockRow = blockIdx.y * 128;
    const int blockCol = blockIdx.x * 256;      // within one of Q/K/V
    const int wrow = (wid >> 2) * 64;
    const int wcol = (wid & 3) * 64;

    const float scale = (blockCol < DIM) ? 0.125f : 1.0f;
    const float* bsel;
    int cb;
    if (blockCol < DIM)            { bsel = bq; cb = blockCol; }
    else if (blockCol < 2 * DIM)   { bsel = bk; cb = blockCol - DIM; }
    else                           { bsel = bv; cb = blockCol - 2 * DIM; }

    float acc[4][8][4];
    #pragma unroll
    for (int mi = 0; mi < 4; mi++)
        #pragma unroll
        for (int ni = 0; ni < 8; ni++)
            #pragma unroll
            for (int j = 0; j < 4; j++) acc[mi][ni][j] = 0.f;

    const int aRow = wrow + (lane & 15);
    const int aCol = (lane >> 4) * 8;
    const int bRow = wcol + (lane >> 4) * 8 + (lane & 7);
    const int bCol = ((lane >> 3) & 1) * 8;

    GEMM_MAINLOOP();

    #pragma unroll
    for (int mi = 0; mi < 4; mi++) {
        const int r0 = blockRow + wrow + mi * 16 + (lane >> 2);
        #pragma unroll
        for (int ni = 0; ni < 8; ni++) {
            const int cc = wcol + ni * 8 + 2 * (lane & 3);
            float2 bv2 = *(const float2*)(bsel + cb + cc);
            const int gc = blockCol + cc;
            float v0x = (acc[mi][ni][0] + bv2.x) * scale;
            float v0y = (acc[mi][ni][1] + bv2.y) * scale;
            float v1x = (acc[mi][ni][2] + bv2.x) * scale;
            float v1y = (acc[mi][ni][3] + bv2.y) * scale;
            uint32_t h0, l0, h1, l1;
            split_pack(v0x, v0y, h0, l0);
            split_pack(v1x, v1y, h1, l1);
            *(uint32_t*)(Ch + (size_t)r0 * NQKV + gc)       = h0;
            *(uint32_t*)(Cl + (size_t)r0 * NQKV + gc)       = l0;
            *(uint32_t*)(Ch + (size_t)(r0 + 8) * NQKV + gc) = h1;
            *(uint32_t*)(Cl + (size_t)(r0 + 8) * NQKV + gc) = l1;
        }
    }
}

// ---------------- O-projection GEMM: fp32 out + bias -----------------------
__global__ __launch_bounds__(256, 1)
void gemm_mma_kernel(const __nv_bfloat16* __restrict__ Ah,
                     const __nv_bfloat16* __restrict__ Al,
                     const __nv_bfloat16* __restrict__ Bh,
                     const __nv_bfloat16* __restrict__ Bl,
                     const float* __restrict__ bias, float* __restrict__ C)
{
    extern __shared__ char smem[];
    const uint32_t sbase = smem_u32(smem);
    const int tid  = threadIdx.x;
    const int wid  = tid >> 5;
    const int lane = tid & 31;
    const int blockRow = blockIdx.y * 128;
    const int blockCol = blockIdx.x * 256;
    const int wrow = (wid >> 2) * 64;
    const int wcol = (wid & 3) * 64;

    float acc[4][8][4];
    #pragma unroll
    for (int mi = 0; mi < 4; mi++)
        #pragma unroll
        for (int ni = 0; ni < 8; ni++)
            #pragma unroll
            for (int j = 0; j < 4; j++) acc[mi][ni][j] = 0.f;

    const int aRow = wrow + (lane & 15);
    const int aCol = (lane >> 4) * 8;
    const int bRow = wcol + (lane >> 4) * 8 + (lane & 7);
    const int bCol = ((lane >> 3) & 1) * 8;

    GEMM_MAINLOOP();

    #pragma unroll
    for (int mi = 0; mi < 4; mi++) {
        const int r0 = blockRow + wrow + mi * 16 + (lane >> 2);
        #pragma unroll
        for (int ni = 0; ni < 8; ni++) {
            const int c0 = blockCol + wcol + ni * 8 + 2 * (lane & 3);
            float2 bv = *(const float2*)(bias + c0);
            float2 v0 = { acc[mi][ni][0] + bv.x, acc[mi][ni][1] + bv.y };
            float2 v1 = { acc[mi][ni][2] + bv.x, acc[mi][ni][3] + bv.y };
            *(float2*)(C + (size_t)r0 * DIM + c0)       = v0;
            *(float2*)(C + (size_t)(r0 + 8) * DIM + c0) = v1;
        }
    }
}

// ---------------- Flash attention (bf16-split mma, causal, softmax-one) ----
// Exact online-max softmax-one; 3-product split for BOTH S and PV (round-14
// proved the PV low-order product is required: dropping it gives 1.1e-3).
// Paired q-tiles {bx, 15-bx} per CTA. Warp-uniform skip of the corr/rescale
// path when no row's max changed this iteration (math identical when taken).
#define FQS 72
#define FQ_ELE   (128 * FQS)
#define FKV_ELE  (64 * FQS)
#define FKVBUF   (4 * FKV_ELE)
#define FLASH_SMEM ((2 * FQ_ELE + 2 * FKVBUF) * 2)   // 110592 bytes

__global__ __launch_bounds__(128, 2) void flash_mma_kernel(
    const __nv_bfloat16* __restrict__ QKVh,
    const __nv_bfloat16* __restrict__ QKVl,
    __nv_bfloat16* __restrict__ Ch,
    __nv_bfloat16* __restrict__ Cl)
{
    const int bx   = blockIdx.x;          // 0..7
    const int bh   = blockIdx.y;          // 0..31
    const int b    = bh >> 4;
    const int h    = bh & 15;
    const int tid  = threadIdx.x;
    const int wid  = tid >> 5;
    const int lane = tid & 31;
    const int wrow = wid * 32;
    const size_t rowbase = (size_t)b * SEQ;
    const int qcol = h * HD;
    const int kcol = qcol + DIM;
    const int vcol = qcol + 2 * DIM;

    extern __shared__ __nv_bfloat16 fsm[];
    const uint32_t uQh = smem_u32(fsm);
    const uint32_t uQl = uQh + FQ_ELE * 2;
    const uint32_t uKV0 = uQl + FQ_ELE * 2;
    #define KV_KH(bb) (uKV0 + (bb) * FKVBUF * 2)
    #define KV_KL(bb) (KV_KH(bb) + FKV_ELE * 2)
    #define KV_VH(bb) (KV_KH(bb) + 2 * FKV_ELE * 2)
    #define KV_VL(bb) (KV_KH(bb) + 3 * FKV_ELE * 2)

    #define ISSUE_Q(qb) { \
        _Pragma("unroll") \
        for (int i = 0; i < 8; i++) { \
            int idx = tid + i * 128; \
            int r = idx >> 3, seg = idx & 7; \
            size_t g = (rowbase + (qb) + r) * NQKV + qcol + seg * 8; \
            cp_async16(uQh + r * 144 + seg * 16, QKVh + g); \
            cp_async16(uQl + r * 144 + seg * 16, QKVl + g); \
        } }

    #define ISSUE_KV(kb, bb) { \
        _Pragma("unroll") \
        for (int i = 0; i < 4; i++) { \
            int idx = tid + i * 128; \
            int r = idx >> 3, seg = idx & 7; \
            size_t gk = (rowbase + (kb) + r) * NQKV + kcol + seg * 8; \
            size_t gv = (rowbase + (kb) + r) * NQKV + vcol + seg * 8; \
            uint32_t so = r * 144 + seg * 16; \
            cp_async16(KV_KH(bb) + so, QKVh + gk); \
            cp_async16(KV_KL(bb) + so, QKVl + gk); \
            cp_async16(KV_VH(bb) + so, QKVh + gv); \
            cp_async16(KV_VL(bb) + so, QKVl + gv); \
        } }

    for (int t = 0; t < 2; t++) {
        const int qt = (t == 0) ? bx : (15 - bx);
        const int qbase = qt * 128;

        float sa[2][8][4];
        float oa[2][8][4];
        float m[4], l[4];
        #pragma unroll
        for (int mi = 0; mi < 2; mi++)
            #pragma unroll
            for (int ni = 0; ni < 8; ni++)
                #pragma unroll
                for (int j = 0; j < 4; j++) oa[mi][ni][j] = 0.f;
        #pragma unroll
        for (int i = 0; i < 4; i++) { m[i] = -INFINITY; l[i] = 0.f; }

        __syncthreads();
        ISSUE_Q(qbase);
        ISSUE_KV(0, 0);
        cp_commit();

        const int nkt = 2 * qt + 2;
        for (int kt = 0; kt < nkt; kt++) {
            const int kbase = kt * 64;
            if (kt + 1 < nkt) { ISSUE_KV((kt + 1) * 64, (kt + 1) & 1); }
            cp_commit();
            if (kt + 1 < nkt) cp_wait<1>(); else cp_wait<0>();
            __syncthreads();

            const int bb = kt & 1;
            const uint32_t uKh = KV_KH(bb), uKl = KV_KL(bb);
            const uint32_t uVh = KV_VH(bb), uVl = KV_VL(bb);

            #pragma unroll
            for (int mi = 0; mi < 2; mi++)
                #pragma unroll
                for (int ni = 0; ni < 8; ni++)
                    #pragma unroll
                    for (int j = 0; j < 4; j++) sa[mi][ni][j] = 0.f;

            // ---- S = Q @ K^T (3-product split) ----
            #pragma unroll
            for (int kk = 0; kk < 4; kk++) {
                uint32_t aqh[2][4], aql[2][4];
                #pragma unroll
                for (int mi = 0; mi < 2; mi++) {
                    uint32_t ao = ((wrow + mi * 16 + (lane & 15)) * FQS +
                                   kk * 16 + (lane >> 4) * 8) * 2;
                    ldsm4(aqh[mi], uQh + ao);
                    ldsm4(aql[mi], uQl + ao);
                }
                #pragma unroll
                for (int g = 0; g < 4; g++) {
                    uint32_t bh_[4], bl_[4];
                    uint32_t bo = ((g * 16 + (lane >> 4) * 8 + (lane & 7)) * FQS +
                                   kk * 16 + ((lane >> 3) & 1) * 8) * 2;
                    ldsm4(bh_, uKh + bo);
                    ldsm4(bl_, uKl + bo);
                    #pragma unroll
                    for (int mi = 0; mi < 2; mi++)
                        #pragma unroll
                        for (int p = 0; p < 2; p++) {
                            int ni = g * 2 + p;
                            mma16816(sa[mi][ni], aqh[mi], &bh_[p * 2]);
                            mma16816(sa[mi][ni], aqh[mi], &bl_[p * 2]);
                            mma16816(sa[mi][ni], aql[mi], &bh_[p * 2]);
                        }
                }
            }

            // ---- causal mask (near-diagonal tiles only) ----
            if (kbase + 63 > qbase + wrow) {
                #pragma unroll
                for (int mi = 0; mi < 2; mi++)
                    #pragma unroll
                    for (int ni = 0; ni < 8; ni++)
                        #pragma unroll
                        for (int j = 0; j < 4; j++) {
                            int qrow = qbase + wrow + mi * 16 + (lane >> 2) + (j >> 1) * 8;
                            int kc = kbase + ni * 8 + 2 * (lane & 3) + (j & 1);
                            if (kc > qrow) sa[mi][ni][j] = -INFINITY;
                        }
            }

            // ---- online softmax-one update (exact row max; uniform skip) ----
            #pragma unroll
            for (int mi = 0; mi < 2; mi++)
                #pragma unroll
                for (int rh = 0; rh < 2; rh++) {
                    const int ri = mi * 2 + rh;
                    float rmax = -INFINITY;
                    #pragma unroll
                    for (int ni = 0; ni < 8; ni++)
                        rmax = fmaxf(rmax, fmaxf(sa[mi][ni][rh * 2], sa[mi][ni][rh * 2 + 1]));
                    rmax = fmaxf(rmax, __shfl_xor_sync(0xffffffffu, rmax, 1));
                    rmax = fmaxf(rmax, __shfl_xor_sync(0xffffffffu, rmax, 2));
                    if (__any_sync(0xffffffffu, rmax > m[ri])) {
                        float mnew = fmaxf(m[ri], rmax);
                        float corr = __expf(m[ri] - mnew);
                        float sum = 0.f;
                        #pragma unroll
                        for (int ni = 0; ni < 8; ni++)
                            #pragma unroll
                            for (int j2 = 0; j2 < 2; j2++) {
                                float p = __expf(sa[mi][ni][rh * 2 + j2] - mnew);
                                sa[mi][ni][rh * 2 + j2] = p;
                                sum += p;
                            }
                        sum += __shfl_xor_sync(0xffffffffu, sum, 1);
                        sum += __shfl_xor_sync(0xffffffffu, sum, 2);
                        l[ri] = l[ri] * corr + sum;
                        m[ri] = mnew;
                        #pragma unroll
                        for (int ni = 0; ni < 8; ni++)
                            #pragma unroll
                            for (int j2 = 0; j2 < 2; j2++)
                                oa[mi][ni][rh * 2 + j2] *= corr;
                    } else {
                        // no row's max changed: corr == 1, m unchanged
                        float sum = 0.f;
                        #pragma unroll
                        for (int ni = 0; ni < 8; ni++)
                            #pragma unroll
                            for (int j2 = 0; j2 < 2; j2++) {
                                float p = __expf(sa[mi][ni][rh * 2 + j2] - m[ri]);
                                sa[mi][ni][rh * 2 + j2] = p;
                                sum += p;
                            }
                        sum += __shfl_xor_sync(0xffffffffu, sum, 1);
                        sum += __shfl_xor_sync(0xffffffffu, sum, 2);
                        l[ri] += sum;
                    }
                }

            // ---- O += P @ V (3-product split; all terms required) ----
            #pragma unroll
            for (int kk = 0; kk < 4; kk++) {
                uint32_t ph[2][4], pl[2][4];
                #pragma unroll
                for (int mi = 0; mi < 2; mi++) {
                    split_pack(sa[mi][2 * kk][0],     sa[mi][2 * kk][1],     ph[mi][0], pl[mi][0]);
                    split_pack(sa[mi][2 * kk][2],     sa[mi][2 * kk][3],     ph[mi][1], pl[mi][1]);
                    split_pack(sa[mi][2 * kk + 1][0], sa[mi][2 * kk + 1][1], ph[mi][2], pl[mi][2]);
                    split_pack(sa[mi][2 * kk + 1][2], sa[mi][2 * kk + 1][3], ph[mi][3], pl[mi][3]);
                }
                #pragma unroll
                for (int dg = 0; dg < 4; dg++) {
                    uint32_t bvh[4], bvl[4];
                    uint32_t bo = ((kk * 16 + ((lane >> 3) & 1) * 8 + (lane & 7)) * FQS +
                                   dg * 16 + (lane >> 4) * 8) * 2;
                    ldsm4t(bvh, uVh + bo);
                    ldsm4t(bvl, uVl + bo);
                    #pragma unroll
                    for (int mi = 0; mi < 2; mi++)
                        #pragma unroll
                        for (int p = 0; p < 2; p++) {
                            int ni = dg * 2 + p;
                            mma16816(oa[mi][ni], ph[mi], &bvh[p * 2]);
                            mma16816(oa[mi][ni], ph[mi], &bvl[p * 2]);
                            mma16816(oa[mi][ni], pl[mi], &bvh[p * 2]);
                        }
                }
            }
            __syncthreads();
        }

        // ---- epilogue: divide by (1 + l), write ctx bf16 hi/lo ----
        #pragma unroll
        for (int mi = 0; mi < 2; mi++) {
            const float inv0 = 1.f / (1.f + l[mi * 2 + 0]);
            const float inv1 = 1.f / (1.f + l[mi * 2 + 1]);
            const int r0 = qbase + wrow + mi * 16 + (lane >> 2);
            #pragma unroll
            for (int ni = 0; ni < 8; ni++) {
                const int c0 = ni * 8 + 2 * (lane & 3);
                uint32_t h0, l0, h1, l1;
                split_pack(oa[mi][ni][0] * inv0, oa[mi][ni][1] * inv0, h0, l0);
                split_pack(oa[mi][ni][2] * inv1, oa[mi][ni][3] * inv1, h1, l1);
                size_t o0 = (rowbase + r0) * DIM + qcol + c0;
                size_t o1 = (rowbase + r0 + 8) * DIM + qcol + c0;
                *(uint32_t*)(Ch + o0) = h0;
                *(uint32_t*)(Cl + o0) = l0;
                *(uint32_t*)(Ch + o1) = h1;
                *(uint32_t*)(Cl + o1) = l1;
            }
        }
    }
}

// ---------------- launcher -------------------------------------------------
extern "C" void kernel_launch(void* const* d_in, const int* in_sizes, int n_in,
                              void* d_out, int out_size)
{
    const float* x  = (const float*)d_in[0];
    const float* Wq = (const float*)d_in[1];
    const float* bq = (const float*)d_in[2];
    const float* Wk = (const float*)d_in[3];
    const float* bk = (const float*)d_in[4];
    const float* Wv = (const float*)d_in[5];
    const float* bv = (const float*)d_in[6];
    const float* Wo = (const float*)d_in[7];
    const float* bo = (const float*)d_in[8];
    float* out = (float*)d_out;

    __nv_bfloat16 *xh, *xl, *wth, *wtl, *qkvh, *qkvl;
    cudaGetSymbolAddress((void**)&xh,   g_xh);
    cudaGetSymbolAddress((void**)&xl,   g_xl);
    cudaGetSymbolAddress((void**)&wth,  g_wth);
    cudaGetSymbolAddress((void**)&wtl,  g_wtl);
    cudaGetSymbolAddress((void**)&qkvh, g_qkvh);
    cudaGetSymbolAddress((void**)&qkvl, g_qkvl);

    cudaFuncSetAttribute(flash_mma_kernel,
                         cudaFuncAttributeMaxDynamicSharedMemorySize, FLASH_SMEM);
    cudaFuncSetAttribute(gemm_qkv_kernel,
                         cudaFuncAttributeMaxDynamicSharedMemorySize, GEMM_SMEM);
    cudaFuncSetAttribute(gemm_mma_kernel,
                         cudaFuncAttributeMaxDynamicSharedMemorySize, GEMM_SMEM);

    // fused prep: z=0..3 weight transpose-split, z=4 x split
    dim3 tg(32, 32, 5);
    prep_kernel<<<tg, 256>>>(x, Wq, Wk, Wv, Wo, wth, wtl, xh, xl);

    dim3 gqkv(NQKV / 256, MROWS / 128);        // (12, 32)
    gemm_qkv_kernel<<<gqkv, 256, GEMM_SMEM>>>(xh, xl, wth, wtl, bq, bk, bv, qkvh, qkvl);

    dim3 attnGrid(SEQ / 256, BATCH * NHEAD);   // (8, 32): paired q-tiles
    flash_mma_kernel<<<attnGrid, 128, FLASH_SMEM>>>(qkvh, qkvl, xh, xl);

    dim3 go(DIM / 256, MROWS / 128);           // (4, 32)
    gemm_mma_kernel<<<go, 256, GEMM_SMEM>>>(xh, xl, wth + 3 * DIM * DIM, wtl + 3 * DIM * DIM, bo, out);
}

// round 16
// speedup vs baseline: 1.1031x; 1.0501x over previous
#include <cuda_runtime.h>
#include <cuda_bf16.h>
#include <math.h>
#include <stdint.h>

#define BATCH 2
#define SEQ   2048
#define DIM   1024
#define NHEAD 16
#define HD    64
#define MROWS (BATCH * SEQ)   // 4096
#define NQKV  (3 * DIM)       // 3072

// ---------------- scratch (device globals; no runtime allocation) ----------
__device__ __nv_bfloat16 g_xh[MROWS * DIM];
__device__ __nv_bfloat16 g_xl[MROWS * DIM];
__device__ __nv_bfloat16 g_wth[4 * DIM * DIM];
__device__ __nv_bfloat16 g_wtl[4 * DIM * DIM];
__device__ __nv_bfloat16 g_qkvh[MROWS * NQKV];
__device__ __nv_bfloat16 g_qkvl[MROWS * NQKV];

// ---------------- PTX helpers (sm_80-era only; no 'a'-gated features) ------
__device__ __forceinline__ uint32_t smem_u32(const void* p) {
    uint32_t a;
    asm("{ .reg .u64 t; cvta.to.shared.u64 t, %1; cvt.u32.u64 %0, t; }"
        : "=r"(a) : "l"(p));
    return a;
}
__device__ __forceinline__ void cp_async16(uint32_t saddr, const void* gptr) {
    asm volatile("cp.async.cg.shared.global [%0], [%1], 16;"
                 :: "r"(saddr), "l"(gptr));
}
__device__ __forceinline__ void cp_commit() {
    asm volatile("cp.async.commit_group;");
}
template <int N>
__device__ __forceinline__ void cp_wait() {
    asm volatile("cp.async.wait_group %0;" :: "n"(N));
}
__device__ __forceinline__ void ldsm4(uint32_t* r, uint32_t addr) {
    asm volatile("ldmatrix.sync.aligned.m8n8.x4.shared.b16 {%0,%1,%2,%3}, [%4];"
                 : "=r"(r[0]), "=r"(r[1]), "=r"(r[2]), "=r"(r[3]) : "r"(addr));
}
__device__ __forceinline__ void ldsm4t(uint32_t* r, uint32_t addr) {
    asm volatile("ldmatrix.sync.aligned.m8n8.x4.trans.shared.b16 {%0,%1,%2,%3}, [%4];"
                 : "=r"(r[0]), "=r"(r[1]), "=r"(r[2]), "=r"(r[3]) : "r"(addr));
}
__device__ __forceinline__ void mma16816(float* c, const uint32_t* a, const uint32_t* b) {
    asm volatile(
        "mma.sync.aligned.m16n8k16.row.col.f32.bf16.bf16.f32 "
        "{%0,%1,%2,%3}, {%4,%5,%6,%7}, {%8,%9}, {%0,%1,%2,%3};"
        : "+f"(c[0]), "+f"(c[1]), "+f"(c[2]), "+f"(c[3])
        : "r"(a[0]), "r"(a[1]), "r"(a[2]), "r"(a[3]), "r"(b[0]), "r"(b[1]));
}
__device__ __forceinline__ uint32_t pack_bf16(float a, float b) {
    __nv_bfloat162 t = __floats2bfloat162_rn(a, b);
    return *(uint32_t*)&t;
}
__device__ __forceinline__ void split_pack(float a, float b, uint32_t& hi, uint32_t& lo) {
    __nv_bfloat16 ah = __float2bfloat16_rn(a);
    __nv_bfloat16 bh = __float2bfloat16_rn(b);
    float al = a - __bfloat162float(ah);
    float bl = b - __bfloat162float(bh);
    __nv_bfloat162 th; th.x = ah; th.y = bh;
    hi = *(uint32_t*)&th;
    lo = pack_bf16(al, bl);
}

// ---------------- split / fused transpose-split kernels ---------------------
__global__ __launch_bounds__(256) void split_kernel(
    const float4* __restrict__ in, __nv_bfloat16* __restrict__ hi,
    __nv_bfloat16* __restrict__ lo, int n4)
{
    int i = blockIdx.x * blockDim.x + threadIdx.x;
    if (i >= n4) return;
    float4 v = in[i];
    float f[4] = {v.x, v.y, v.z, v.w};
    __nv_bfloat162 h2[2], l2[2];
    #pragma unroll
    for (int j = 0; j < 4; j++) {
        __nv_bfloat16 h = __float2bfloat16_rn(f[j]);
        __nv_bfloat16 l = __float2bfloat16_rn(f[j] - __bfloat162float(h));
        ((__nv_bfloat16*)h2)[j] = h;
        ((__nv_bfloat16*)l2)[j] = l;
    }
    ((__nv_bfloat162*)hi)[2 * i + 0] = h2[0];
    ((__nv_bfloat162*)hi)[2 * i + 1] = h2[1];
    ((__nv_bfloat162*)lo)[2 * i + 0] = l2[0];
    ((__nv_bfloat162*)lo)[2 * i + 1] = l2[1];
}

// all 4 weights: W[K,N] fp32 -> Th/Tl [N,K] bf16 ; blockIdx.z picks the weight
__global__ __launch_bounds__(256) void transpose_split4_kernel(
    const float* __restrict__ W0, const float* __restrict__ W1,
    const float* __restrict__ W2, const float* __restrict__ W3,
    __nv_bfloat16* __restrict__ Th, __nv_bfloat16* __restrict__ Tl)
{
    __shared__ float t[32][33];
    const int z = blockIdx.z;
    const float* W = (z == 0) ? W0 : (z == 1) ? W1 : (z == 2) ? W2 : W3;
    __nv_bfloat16* Tho = Th + (size_t)z * DIM * DIM;
    __nv_bfloat16* Tlo = Tl + (size_t)z * DIM * DIM;
    const int tx = threadIdx.x & 31, ty = threadIdx.x >> 5;
    const int bx = blockIdx.x * 32, by = blockIdx.y * 32;
    #pragma unroll
    for (int s = 0; s < 4; s++)
        t[ty + s * 8][tx] = W[(size_t)(by + ty + s * 8) * DIM + bx + tx];
    __syncthreads();
    #pragma unroll
    for (int s = 0; s < 4; s++) {
        float v = t[tx][ty + s * 8];
        __nv_bfloat16 h = __float2bfloat16_rn(v);
        __nv_bfloat16 l = __float2bfloat16_rn(v - __bfloat162float(h));
        size_t o = (size_t)(bx + ty + s * 8) * DIM + by + tx;
        Tho[o] = h; Tlo[o] = l;
    }
}

// ---------------- shared GEMM plumbing: 128x256 tile, K=64 chunks, 2 stages -
// Single-sync pipeline: wait<0>; sync; issue c+1; compute c.
// WAR-safe: buffer (c+1)&1 last read in iteration c-1, and all warps passed
// the sync (placed before the issue) after that read.
#define GS3   72                          // row stride (elems) = 144 B
#define AT3   (128 * GS3 * 2)             // 18432 B (A tile)
#define BT3   (256 * GS3 * 2)             // 36864 B (B tile)
#define GB3   (2 * AT3 + 2 * BT3)         // 110592 B per stage
#define GEMM_SMEM (2 * GB3)               // 221184 B (2 stages)
#define NCH3  (DIM / 64)                  // 16 chunks

#define ISSUE_CHUNK3(c, buf, bRowBase) { \
    const int ko_ = (c) * 64; \
    uint32_t s0 = sbase + (buf) * GB3; \
    _Pragma("unroll") \
    for (int i = 0; i < 4; i++) { \
        int idx = tid + i * 256; \
        int row = idx >> 3, seg = idx & 7; \
        uint32_t so = row * 144 + seg * 16; \
        cp_async16(s0 + so,       Ah + (size_t)(blockRow + row) * DIM + ko_ + seg * 8); \
        cp_async16(s0 + AT3 + so, Al + (size_t)(blockRow + row) * DIM + ko_ + seg * 8); \
    } \
    _Pragma("unroll") \
    for (int i = 0; i < 8; i++) { \
        int idx = tid + i * 256; \
        int row = idx >> 3, seg = idx & 7; \
        uint32_t so = row * 144 + seg * 16; \
        cp_async16(s0 + 2 * AT3 + so,       Bh + (size_t)((bRowBase) + row) * DIM + ko_ + seg * 8); \
        cp_async16(s0 + 2 * AT3 + BT3 + so, Bl + (size_t)((bRowBase) + row) * DIM + ko_ + seg * 8); \
    } }

#define GEMM_MAINLOOP() \
    ISSUE_CHUNK3(0, 0, blockCol); \
    cp_commit(); \
    for (int c = 0; c < NCH3; c++) { \
        cp_wait<0>(); \
        __syncthreads(); \
        if (c + 1 < NCH3) { ISSUE_CHUNK3(c + 1, (c + 1) & 1, blockCol); cp_commit(); } \
        const uint32_t s0 = sbase + (c & 1) * GB3; \
        _Pragma("unroll") \
        for (int kk = 0; kk < 4; kk++) { \
            uint32_t ah[4][4], al[4][4], bhf[4][4], blf[4][4]; \
            _Pragma("unroll") \
            for (int mi = 0; mi < 4; mi++) { \
                uint32_t ao = ((aRow + mi * 16) * GS3 + kk * 16 + aCol) * 2; \
                ldsm4(ah[mi], s0 + ao); \
                ldsm4(al[mi], s0 + AT3 + ao); \
            } \
            _Pragma("unroll") \
            for (int g = 0; g < 4; g++) { \
                uint32_t bo = ((bRow + g * 16) * GS3 + kk * 16 + bCol) * 2; \
                ldsm4(bhf[g], s0 + 2 * AT3 + bo); \
                ldsm4(blf[g], s0 + 2 * AT3 + BT3 + bo); \
            } \
            _Pragma("unroll") \
            for (int mi = 0; mi < 4; mi++) \
                _Pragma("unroll") \
                for (int ni = 0; ni < 8; ni++) { \
                    mma16816(acc[mi][ni], ah[mi], &bhf[ni >> 1][(ni & 1) * 2]); \
                    mma16816(acc[mi][ni], ah[mi], &blf[ni >> 1][(ni & 1) * 2]); \
                    mma16816(acc[mi][ni], al[mi], &bhf[ni >> 1][(ni & 1) * 2]); \
                } \
        } \
    }

// ---------------- fused QKV GEMM: writes bf16 hi/lo, Q scaled by 0.125 -----
__global__ __launch_bounds__(256, 1)
void gemm_qkv_kernel(const __nv_bfloat16* __restrict__ Ah,
                     const __nv_bfloat16* __restrict__ Al,
                     const __nv_bfloat16* __restrict__ Bh,
                     const __nv_bfloat16* __restrict__ Bl,
                     const float* __restrict__ bq,
                     const float* __restrict__ bk,
                     const float* __restrict__ bv,
                     __nv_bfloat16* __restrict__ Ch,
                     __nv_bfloat16* __restrict__ Cl)
{
    extern __shared__ char smem[];
    const uint32_t sbase = smem_u32(smem);
    const int tid  = threadIdx.x;
    const int wid  = tid >> 5;
    const int lane = tid & 31;
    const int blockRow = blockIdx.y * 128;
    const int blockCol = blockIdx.x * 256;      // within one of Q/K/V
    const int wrow = (wid >> 2) * 64;
    const int wcol = (wid & 3) * 64;

    const float scale = (blockCol < DIM) ? 0.125f : 1.0f;
    const float* bsel;
    int cb;
    if (blockCol < DIM)            { bsel = bq; cb = blockCol; }
    else if (blockCol < 2 * DIM)   { bsel = bk; cb = blockCol - DIM; }
    else                           { bsel = bv; cb = blockCol - 2 * DIM; }

    float acc[4][8][4];
    #pragma unroll
    for (int mi = 0; mi < 4; mi++)
        #pragma unroll
        for (int ni = 0; ni < 8; ni++)
            #pragma unroll
            for (int j = 0; j < 4; j++) acc[mi][ni][j] = 0.f;

    const int aRow = wrow + (lane & 15);
    const int aCol = (lane >> 4) * 8;
    const int bRow = wcol + (lane >> 4) * 8 + (lane & 7);
    const int bCol = ((lane >> 3) & 1) * 8;

    GEMM_MAINLOOP();

    #pragma unroll
    for (int mi = 0; mi < 4; mi++) {
        const int r0 = blockRow + wrow + mi * 16 + (lane >> 2);
        #pragma unroll
        for (int ni = 0; ni < 8; ni++) {
            const int cc = wcol + ni * 8 + 2 * (lane & 3);
            float2 bv2 = *(const float2*)(bsel + cb + cc);
            const int gc = blockCol + cc;
            float v0x = (acc[mi][ni][0] + bv2.x) * scale;
            float v0y = (acc[mi][ni][1] + bv2.y) * scale;
            float v1x = (acc[mi][ni][2] + bv2.x) * scale;
            float v1y = (acc[mi][ni][3] + bv2.y) * scale;
            uint32_t h0, l0, h1, l1;
            split_pack(v0x, v0y, h0, l0);
            split_pack(v1x, v1y, h1, l1);
            *(uint32_t*)(Ch + (size_t)r0 * NQKV + gc)       = h0;
            *(uint32_t*)(Cl + (size_t)r0 * NQKV + gc)       = l0;
            *(uint32_t*)(Ch + (size_t)(r0 + 8) * NQKV + gc) = h1;
            *(uint32_t*)(Cl + (size_t)(r0 + 8) * NQKV + gc) = l1;
        }
    }
}

// ---------------- O-projection GEMM: fp32 out + bias -----------------------
__global__ __launch_bounds__(256, 1)
void gemm_mma_kernel(const __nv_bfloat16* __restrict__ Ah,
                     const __nv_bfloat16* __restrict__ Al,
                     const __nv_bfloat16* __restrict__ Bh,
                     const __nv_bfloat16* __restrict__ Bl,
                     const float* __restrict__ bias, float* __restrict__ C)
{
    extern __shared__ char smem[];
    const uint32_t sbase = smem_u32(smem);
    const int tid  = threadIdx.x;
    const int wid  = tid >> 5;
    const int lane = tid & 31;
    const int blockRow = blockIdx.y * 128;
    const int blockCol = blockIdx.x * 256;
    const int wrow = (wid >> 2) * 64;
    const int wcol = (wid & 3) * 64;

    float acc[4][8][4];
    #pragma unroll
    for (int mi = 0; mi < 4; mi++)
        #pragma unroll
        for (int ni = 0; ni < 8; ni++)
            #pragma unroll
            for (int j = 0; j < 4; j++) acc[mi][ni][j] = 0.f;

    const int aRow = wrow + (lane & 15);
    const int aCol = (lane >> 4) * 8;
    const int bRow = wcol + (lane >> 4) * 8 + (lane & 7);
    const int bCol = ((lane >> 3) & 1) * 8;

    GEMM_MAINLOOP();

    #pragma unroll
    for (int mi = 0; mi < 4; mi++) {
        const int r0 = blockRow + wrow + mi * 16 + (lane >> 2);
        #pragma unroll
        for (int ni = 0; ni < 8; ni++) {
            const int c0 = blockCol + wcol + ni * 8 + 2 * (lane & 3);
            float2 bv = *(const float2*)(bias + c0);
            float2 v0 = { acc[mi][ni][0] + bv.x, acc[mi][ni][1] + bv.y };
            float2 v1 = { acc[mi][ni][2] + bv.x, acc[mi][ni][3] + bv.y };
            *(float2*)(C + (size_t)r0 * DIM + c0)       = v0;
            *(float2*)(C + (size_t)(r0 + 8) * DIM + c0) = v1;
        }
    }
}

// ---------------- Flash attention (bf16-split mma, causal, softmax-one) ----
// Round-11 math exactly (online-max softmax-one; 3-product S and PV; paired
// q-tiles). Single-sync pipeline: wait<0>; sync; issue KV kt+1; compute.
#define FQS 72
#define FQ_ELE   (128 * FQS)
#define FKV_ELE  (64 * FQS)
#define FKVBUF   (4 * FKV_ELE)
#define FLASH_SMEM ((2 * FQ_ELE + 2 * FKVBUF) * 2)   // 110592 bytes

__global__ __launch_bounds__(128, 2) void flash_mma_kernel(
    const __nv_bfloat16* __restrict__ QKVh,
    const __nv_bfloat16* __restrict__ QKVl,
    __nv_bfloat16* __restrict__ Ch,
    __nv_bfloat16* __restrict__ Cl)
{
    const int bx   = blockIdx.x;          // 0..7
    const int bh   = blockIdx.y;          // 0..31
    const int b    = bh >> 4;
    const int h    = bh & 15;
    const int tid  = threadIdx.x;
    const int wid  = tid >> 5;
    const int lane = tid & 31;
    const int wrow = wid * 32;
    const size_t rowbase = (size_t)b * SEQ;
    const int qcol = h * HD;
    const int kcol = qcol + DIM;
    const int vcol = qcol + 2 * DIM;

    extern __shared__ __nv_bfloat16 fsm[];
    const uint32_t uQh = smem_u32(fsm);
    const uint32_t uQl = uQh + FQ_ELE * 2;
    const uint32_t uKV0 = uQl + FQ_ELE * 2;
    #define KV_KH(bb) (uKV0 + (bb) * FKVBUF * 2)
    #define KV_KL(bb) (KV_KH(bb) + FKV_ELE * 2)
    #define KV_VH(bb) (KV_KH(bb) + 2 * FKV_ELE * 2)
    #define KV_VL(bb) (KV_KH(bb) + 3 * FKV_ELE * 2)

    #define ISSUE_Q(qb) { \
        _Pragma("unroll") \
        for (int i = 0; i < 8; i++) { \
            int idx = tid + i * 128; \
            int r = idx >> 3, seg = idx & 7; \
            size_t g = (rowbase + (qb) + r) * NQKV + qcol + seg * 8; \
            cp_async16(uQh + r * 144 + seg * 16, QKVh + g); \
            cp_async16(uQl + r * 144 + seg * 16, QKVl + g); \
        } }

    #define ISSUE_KV(kb, bb) { \
        _Pragma("unroll") \
        for (int i = 0; i < 4; i++) { \
            int idx = tid + i * 128; \
            int r = idx >> 3, seg = idx & 7; \
            size_t gk = (rowbase + (kb) + r) * NQKV + kcol + seg * 8; \
            size_t gv = (rowbase + (kb) + r) * NQKV + vcol + seg * 8; \
            uint32_t so = r * 144 + seg * 16; \
            cp_async16(KV_KH(bb) + so, QKVh + gk); \
            cp_async16(KV_KL(bb) + so, QKVl + gk); \
            cp_async16(KV_VH(bb) + so, QKVh + gv); \
            cp_async16(KV_VL(bb) + so, QKVl + gv); \
        } }

    for (int t = 0; t < 2; t++) {
        const int qt = (t == 0) ? bx : (15 - bx);
        const int qbase = qt * 128;

        float sa[2][8][4];
        float oa[2][8][4];
        float m[4], l[4];
        #pragma unroll
        for (int mi = 0; mi < 2; mi++)
            #pragma unroll
            for (int ni = 0; ni < 8; ni++)
                #pragma unroll
                for (int j = 0; j < 4; j++) oa[mi][ni][j] = 0.f;
        #pragma unroll
        for (int i = 0; i < 4; i++) { m[i] = -INFINITY; l[i] = 0.f; }

        __syncthreads();          // prior tile's smem readers done
        ISSUE_Q(qbase);
        ISSUE_KV(0, 0);
        cp_commit();

        const int nkt = 2 * qt + 2;
        for (int kt = 0; kt < nkt; kt++) {
            const int kbase = kt * 64;
            cp_wait<0>();
            __syncthreads();
            if (kt + 1 < nkt) { ISSUE_KV((kt + 1) * 64, (kt + 1) & 1); cp_commit(); }

            const int bb = kt & 1;
            const uint32_t uKh = KV_KH(bb), uKl = KV_KL(bb);
            const uint32_t uVh = KV_VH(bb), uVl = KV_VL(bb);

            #pragma unroll
            for (int mi = 0; mi < 2; mi++)
                #pragma unroll
                for (int ni = 0; ni < 8; ni++)
                    #pragma unroll
                    for (int j = 0; j < 4; j++) sa[mi][ni][j] = 0.f;

            // ---- S = Q @ K^T (3-product split) ----
            #pragma unroll
            for (int kk = 0; kk < 4; kk++) {
                uint32_t aqh[2][4], aql[2][4];
                #pragma unroll
                for (int mi = 0; mi < 2; mi++) {
                    uint32_t ao = ((wrow + mi * 16 + (lane & 15)) * FQS +
                                   kk * 16 + (lane >> 4) * 8) * 2;
                    ldsm4(aqh[mi], uQh + ao);
                    ldsm4(aql[mi], uQl + ao);
                }
                #pragma unroll
                for (int g = 0; g < 4; g++) {
                    uint32_t bh_[4], bl_[4];
                    uint32_t bo = ((g * 16 + (lane >> 4) * 8 + (lane & 7)) * FQS +
                                   kk * 16 + ((lane >> 3) & 1) * 8) * 2;
                    ldsm4(bh_, uKh + bo);
                    ldsm4(bl_, uKl + bo);
                    #pragma unroll
                    for (int mi = 0; mi < 2; mi++)
                        #pragma unroll
                        for (int p = 0; p < 2; p++) {
                            int ni = g * 2 + p;
                            mma16816(sa[mi][ni], aqh[mi], &bh_[p * 2]);
                            mma16816(sa[mi][ni], aqh[mi], &bl_[p * 2]);
                            mma16816(sa[mi][ni], aql[mi], &bh_[p * 2]);
                        }
                }
            }

            // ---- causal mask (near-diagonal tiles only) ----
            if (kbase + 63 > qbase + wrow) {
                #pragma unroll
                for (int mi = 0; mi < 2; mi++)
                    #pragma unroll
                    for (int ni = 0; ni < 8; ni++)
                        #pragma unroll
                        for (int j = 0; j < 4; j++) {
                            int qrow = qbase + wrow + mi * 16 + (lane >> 2) + (j >> 1) * 8;
                            int kc = kbase + ni * 8 + 2 * (lane & 3) + (j & 1);
                            if (kc > qrow) sa[mi][ni][j] = -INFINITY;
                        }
            }

            // ---- online softmax-one update (exact row max) ----
            #pragma unroll
            for (int mi = 0; mi < 2; mi++)
                #pragma unroll
                for (int rh = 0; rh < 2; rh++) {
                    const int ri = mi * 2 + rh;
                    float rmax = -INFINITY;
                    #pragma unroll
                    for (int ni = 0; ni < 8; ni++)
                        rmax = fmaxf(rmax, fmaxf(sa[mi][ni][rh * 2], sa[mi][ni][rh * 2 + 1]));
                    rmax = fmaxf(rmax, __shfl_xor_sync(0xffffffffu, rmax, 1));
                    rmax = fmaxf(rmax, __shfl_xor_sync(0xffffffffu, rmax, 2));
                    float mnew = fmaxf(m[ri], rmax);
                    float corr = __expf(m[ri] - mnew);
                    float sum = 0.f;
                    #pragma unroll
                    for (int ni = 0; ni < 8; ni++)
                        #pragma unroll
                        for (int j2 = 0; j2 < 2; j2++) {
                            float p = __expf(sa[mi][ni][rh * 2 + j2] - mnew);
                            sa[mi][ni][rh * 2 + j2] = p;
                            sum += p;
                        }
                    sum += __shfl_xor_sync(0xffffffffu, sum, 1);
                    sum += __shfl_xor_sync(0xffffffffu, sum, 2);
                    l[ri] = l[ri] * corr + sum;
                    m[ri] = mnew;
                    #pragma unroll
                    for (int ni = 0; ni < 8; ni++)
                        #pragma unroll
                        for (int j2 = 0; j2 < 2; j2++)
                            oa[mi][ni][rh * 2 + j2] *= corr;
                }

            // ---- O += P @ V (3-product split) ----
            #pragma unroll
            for (int kk = 0; kk < 4; kk++) {
                uint32_t ph[2][4], pl[2][4];
                #pragma unroll
                for (int mi = 0; mi < 2; mi++) {
                    split_pack(sa[mi][2 * kk][0],     sa[mi][2 * kk][1],     ph[mi][0], pl[mi][0]);
                    split_pack(sa[mi][2 * kk][2],     sa[mi][2 * kk][3],     ph[mi][1], pl[mi][1]);
                    split_pack(sa[mi][2 * kk + 1][0], sa[mi][2 * kk + 1][1], ph[mi][2], pl[mi][2]);
                    split_pack(sa[mi][2 * kk + 1][2], sa[mi][2 * kk + 1][3], ph[mi][3], pl[mi][3]);
                }
                #pragma unroll
                for (int dg = 0; dg < 4; dg++) {
                    uint32_t bvh[4], bvl[4];
                    uint32_t bo = ((kk * 16 + ((lane >> 3) & 1) * 8 + (lane & 7)) * FQS +
                                   dg * 16 + (lane >> 4) * 8) * 2;
                    ldsm4t(bvh, uVh + bo);
                    ldsm4t(bvl, uVl + bo);
                    #pragma unroll
                    for (int mi = 0; mi < 2; mi++)
                        #pragma unroll
                        for (int p = 0; p < 2; p++) {
                            int ni = dg * 2 + p;
                            mma16816(oa[mi][ni], ph[mi], &bvh[p * 2]);
                            mma16816(oa[mi][ni], ph[mi], &bvl[p * 2]);
                            mma16816(oa[mi][ni], pl[mi], &bvh[p * 2]);
                        }
                }
            }
        }

        // ---- epilogue: divide by (1 + l), write ctx bf16 hi/lo ----
        #pragma unroll
        for (int mi = 0; mi < 2; mi++) {
            const float inv0 = 1.f / (1.f + l[mi * 2 + 0]);
            const float inv1 = 1.f / (1.f + l[mi * 2 + 1]);
            const int r0 = qbase + wrow + mi * 16 + (lane >> 2);
            #pragma unroll
            for (int ni = 0; ni < 8; ni++) {
                const int c0 = ni * 8 + 2 * (lane & 3);
                uint32_t h0, l0, h1, l1;
                split_pack(oa[mi][ni][0] * inv0, oa[mi][ni][1] * inv0, h0, l0);
                split_pack(oa[mi][ni][2] * inv1, oa[mi][ni][3] * inv1, h1, l1);
                size_t o0 = (rowbase + r0) * DIM + qcol + c0;
                size_t o1 = (rowbase + r0 + 8) * DIM + qcol + c0;
                *(uint32_t*)(Ch + o0) = h0;
                *(uint32_t*)(Cl + o0) = l0;
                *(uint32_t*)(Ch + o1) = h1;
                *(uint32_t*)(Cl + o1) = l1;
            }
        }
    }
}

// ---------------- launcher -------------------------------------------------
extern "C" void kernel_launch(void* const* d_in, const int* in_sizes, int n_in,
                              void* d_out, int out_size)
{
    const float* x  = (const float*)d_in[0];
    const float* Wq = (const float*)d_in[1];
    const float* bq = (const float*)d_in[2];
    const float* Wk = (const float*)d_in[3];
    const float* bk = (const float*)d_in[4];
    const float* Wv = (const float*)d_in[5];
    const float* bv = (const float*)d_in[6];
    const float* Wo = (const float*)d_in[7];
    const float* bo = (const float*)d_in[8];
    float* out = (float*)d_out;

    __nv_bfloat16 *xh, *xl, *wth, *wtl, *qkvh, *qkvl;
    cudaGetSymbolAddress((void**)&xh,   g_xh);
    cudaGetSymbolAddress((void**)&xl,   g_xl);
    cudaGetSymbolAddress((void**)&wth,  g_wth);
    cudaGetSymbolAddress((void**)&wtl,  g_wtl);
    cudaGetSymbolAddress((void**)&qkvh, g_qkvh);
    cudaGetSymbolAddress((void**)&qkvl, g_qkvl);

    cudaFuncSetAttribute(flash_mma_kernel,
                         cudaFuncAttributeMaxDynamicSharedMemorySize, FLASH_SMEM);
    cudaFuncSetAttribute(gemm_qkv_kernel,
                         cudaFuncAttributeMaxDynamicSharedMemorySize, GEMM_SMEM);
    cudaFuncSetAttribute(gemm_mma_kernel,
                         cudaFuncAttributeMaxDynamicSharedMemorySize, GEMM_SMEM);

    const int n4 = MROWS * DIM / 4;

    split_kernel<<<(n4 + 255) / 256, 256>>>((const float4*)x, xh, xl, n4);
    dim3 tg(32, 32, 4);
    transpose_split4_kernel<<<tg, 256>>>(Wq, Wk, Wv, Wo, wth, wtl);

    dim3 gqkv(NQKV / 256, MROWS / 128);        // (12, 32)
    gemm_qkv_kernel<<<gqkv, 256, GEMM_SMEM>>>(xh, xl, wth, wtl, bq, bk, bv, qkvh, qkvl);

    dim3 attnGrid(SEQ / 256, BATCH * NHEAD);   // (8, 32): paired q-tiles
    flash_mma_kernel<<<attnGrid, 128, FLASH_SMEM>>>(qkvh, qkvl, xh, xl);

    dim3 go(DIM / 256, MROWS / 128);           // (4, 32)
    gemm_mma_kernel<<<go, 256, GEMM_SMEM>>>(xh, xl, wth + 3 * DIM * DIM, wtl + 3 * DIM * DIM, bo, out);
}

// round 17
// speedup vs baseline: 1.1151x; 1.0109x over previous
#include <cuda_runtime.h>
#include <cuda_bf16.h>
#include <math.h>
#include <stdint.h>

#define BATCH 2
#define SEQ   2048
#define DIM   1024
#define NHEAD 16
#define HD    64
#define MROWS (BATCH * SEQ)   // 4096
#define NQKV  (3 * DIM)       // 3072

// ---------------- scratch (device globals; no runtime allocation) ----------
__device__ __nv_bfloat16 g_xh[MROWS * DIM];
__device__ __nv_bfloat16 g_xl[MROWS * DIM];
__device__ __nv_bfloat16 g_wth[4 * DIM * DIM];
__device__ __nv_bfloat16 g_wtl[4 * DIM * DIM];
__device__ __nv_bfloat16 g_qkvh[MROWS * NQKV];
__device__ __nv_bfloat16 g_qkvl[MROWS * NQKV];

// ---------------- PTX helpers (sm_80-era only; no 'a'-gated features) ------
__device__ __forceinline__ uint32_t smem_u32(const void* p) {
    uint32_t a;
    asm("{ .reg .u64 t; cvta.to.shared.u64 t, %1; cvt.u32.u64 %0, t; }"
        : "=r"(a) : "l"(p));
    return a;
}
__device__ __forceinline__ void cp_async16(uint32_t saddr, const void* gptr) {
    asm volatile("cp.async.cg.shared.global [%0], [%1], 16;"
                 :: "r"(saddr), "l"(gptr));
}
__device__ __forceinline__ void cp_commit() {
    asm volatile("cp.async.commit_group;");
}
template <int N>
__device__ __forceinline__ void cp_wait() {
    asm volatile("cp.async.wait_group %0;" :: "n"(N));
}
__device__ __forceinline__ void ldsm4(uint32_t* r, uint32_t addr) {
    asm volatile("ldmatrix.sync.aligned.m8n8.x4.shared.b16 {%0,%1,%2,%3}, [%4];"
                 : "=r"(r[0]), "=r"(r[1]), "=r"(r[2]), "=r"(r[3]) : "r"(addr));
}
__device__ __forceinline__ void ldsm4t(uint32_t* r, uint32_t addr) {
    asm volatile("ldmatrix.sync.aligned.m8n8.x4.trans.shared.b16 {%0,%1,%2,%3}, [%4];"
                 : "=r"(r[0]), "=r"(r[1]), "=r"(r[2]), "=r"(r[3]) : "r"(addr));
}
__device__ __forceinline__ void mma16816(float* c, const uint32_t* a, const uint32_t* b) {
    asm volatile(
        "mma.sync.aligned.m16n8k16.row.col.f32.bf16.bf16.f32 "
        "{%0,%1,%2,%3}, {%4,%5,%6,%7}, {%8,%9}, {%0,%1,%2,%3};"
        : "+f"(c[0]), "+f"(c[1]), "+f"(c[2]), "+f"(c[3])
        : "r"(a[0]), "r"(a[1]), "r"(a[2]), "r"(a[3]), "r"(b[0]), "r"(b[1]));
}
__device__ __forceinline__ uint32_t pack_bf16(float a, float b) {
    __nv_bfloat162 t = __floats2bfloat162_rn(a, b);
    return *(uint32_t*)&t;
}
__device__ __forceinline__ void split_pack(float a, float b, uint32_t& hi, uint32_t& lo) {
    __nv_bfloat16 ah = __float2bfloat16_rn(a);
    __nv_bfloat16 bh = __float2bfloat16_rn(b);
    float al = a - __bfloat162float(ah);
    float bl = b - __bfloat162float(bh);
    __nv_bfloat162 th; th.x = ah; th.y = bh;
    hi = *(uint32_t*)&th;
    lo = pack_bf16(al, bl);
}
// truncation split: hi = top-16-bits (1 PRMT for the pair), lo = exact residual
__device__ __forceinline__ void split_pack_trunc(float a, float b, uint32_t& hi, uint32_t& lo) {
    uint32_t ua = __float_as_uint(a), ub = __float_as_uint(b);
    hi = __byte_perm(ua, ub, 0x7632);
    float la = a - __uint_as_float(ua & 0xFFFF0000u);
    float lb = b - __uint_as_float(ub & 0xFFFF0000u);
    lo = pack_bf16(la, lb);
}
// bare MUFU exp2 (scores are pre-scaled by log2e)
__device__ __forceinline__ float ex2(float x) {
    float r; asm("ex2.approx.f32 %0, %1;" : "=f"(r) : "f"(x)); return r;
}

// ---------------- split / fused transpose-split kernels ---------------------
__global__ __launch_bounds__(256) void split_kernel(
    const float4* __restrict__ in, __nv_bfloat16* __restrict__ hi,
    __nv_bfloat16* __restrict__ lo, int n4)
{
    int i = blockIdx.x * blockDim.x + threadIdx.x;
    if (i >= n4) return;
    float4 v = in[i];
    float f[4] = {v.x, v.y, v.z, v.w};
    __nv_bfloat162 h2[2], l2[2];
    #pragma unroll
    for (int j = 0; j < 4; j++) {
        __nv_bfloat16 h = __float2bfloat16_rn(f[j]);
        __nv_bfloat16 l = __float2bfloat16_rn(f[j] - __bfloat162float(h));
        ((__nv_bfloat16*)h2)[j] = h;
        ((__nv_bfloat16*)l2)[j] = l;
    }
    ((__nv_bfloat162*)hi)[2 * i + 0] = h2[0];
    ((__nv_bfloat162*)hi)[2 * i + 1] = h2[1];
    ((__nv_bfloat162*)lo)[2 * i + 0] = l2[0];
    ((__nv_bfloat162*)lo)[2 * i + 1] = l2[1];
}

// all 4 weights: W[K,N] fp32 -> Th/Tl [N,K] bf16 ; blockIdx.z picks the weight
__global__ __launch_bounds__(256) void transpose_split4_kernel(
    const float* __restrict__ W0, const float* __restrict__ W1,
    const float* __restrict__ W2, const float* __restrict__ W3,
    __nv_bfloat16* __restrict__ Th, __nv_bfloat16* __restrict__ Tl)
{
    __shared__ float t[32][33];
    const int z = blockIdx.z;
    const float* W = (z == 0) ? W0 : (z == 1) ? W1 : (z == 2) ? W2 : W3;
    __nv_bfloat16* Tho = Th + (size_t)z * DIM * DIM;
    __nv_bfloat16* Tlo = Tl + (size_t)z * DIM * DIM;
    const int tx = threadIdx.x & 31, ty = threadIdx.x >> 5;
    const int bx = blockIdx.x * 32, by = blockIdx.y * 32;
    #pragma unroll
    for (int s = 0; s < 4; s++)
        t[ty + s * 8][tx] = W[(size_t)(by + ty + s * 8) * DIM + bx + tx];
    __syncthreads();
    #pragma unroll
    for (int s = 0; s < 4; s++) {
        float v = t[tx][ty + s * 8];
        __nv_bfloat16 h = __float2bfloat16_rn(v);
        __nv_bfloat16 l = __float2bfloat16_rn(v - __bfloat162float(h));
        size_t o = (size_t)(bx + ty + s * 8) * DIM + by + tx;
        Tho[o] = h; Tlo[o] = l;
    }
}

// ---------------- shared GEMM plumbing: 128x256 tile, K=64 chunks, 2 stages -
// Single-sync pipeline: wait<0>; sync; issue c+1; compute c.
#define GS3   72                          // row stride (elems) = 144 B
#define AT3   (128 * GS3 * 2)             // 18432 B (A tile)
#define BT3   (256 * GS3 * 2)             // 36864 B (B tile)
#define GB3   (2 * AT3 + 2 * BT3)         // 110592 B per stage
#define GEMM_SMEM (2 * GB3)               // 221184 B (2 stages)
#define NCH3  (DIM / 64)                  // 16 chunks

#define ISSUE_CHUNK3(c, buf, bRowBase) { \
    const int ko_ = (c) * 64; \
    uint32_t s0 = sbase + (buf) * GB3; \
    _Pragma("unroll") \
    for (int i = 0; i < 4; i++) { \
        int idx = tid + i * 256; \
        int row = idx >> 3, seg = idx & 7; \
        uint32_t so = row * 144 + seg * 16; \
        cp_async16(s0 + so,       Ah + (size_t)(blockRow + row) * DIM + ko_ + seg * 8); \
        cp_async16(s0 + AT3 + so, Al + (size_t)(blockRow + row) * DIM + ko_ + seg * 8); \
    } \
    _Pragma("unroll") \
    for (int i = 0; i < 8; i++) { \
        int idx = tid + i * 256; \
        int row = idx >> 3, seg = idx & 7; \
        uint32_t so = row * 144 + seg * 16; \
        cp_async16(s0 + 2 * AT3 + so,       Bh + (size_t)((bRowBase) + row) * DIM + ko_ + seg * 8); \
        cp_async16(s0 + 2 * AT3 + BT3 + so, Bl + (size_t)((bRowBase) + row) * DIM + ko_ + seg * 8); \
    } }

#define GEMM_MAINLOOP() \
    ISSUE_CHUNK3(0, 0, blockCol); \
    cp_commit(); \
    for (int c = 0; c < NCH3; c++) { \
        cp_wait<0>(); \
        __syncthreads(); \
        if (c + 1 < NCH3) { ISSUE_CHUNK3(c + 1, (c + 1) & 1, blockCol); cp_commit(); } \
        const uint32_t s0 = sbase + (c & 1) * GB3; \
        _Pragma("unroll") \
        for (int kk = 0; kk < 4; kk++) { \
            uint32_t ah[4][4], al[4][4], bhf[4][4], blf[4][4]; \
            _Pragma("unroll") \
            for (int mi = 0; mi < 4; mi++) { \
                uint32_t ao = ((aRow + mi * 16) * GS3 + kk * 16 + aCol) * 2; \
                ldsm4(ah[mi], s0 + ao); \
                ldsm4(al[mi], s0 + AT3 + ao); \
            } \
            _Pragma("unroll") \
            for (int g = 0; g < 4; g++) { \
                uint32_t bo = ((bRow + g * 16) * GS3 + kk * 16 + bCol) * 2; \
                ldsm4(bhf[g], s0 + 2 * AT3 + bo); \
                ldsm4(blf[g], s0 + 2 * AT3 + BT3 + bo); \
            } \
            _Pragma("unroll") \
            for (int mi = 0; mi < 4; mi++) \
                _Pragma("unroll") \
                for (int ni = 0; ni < 8; ni++) { \
                    mma16816(acc[mi][ni], ah[mi], &bhf[ni >> 1][(ni & 1) * 2]); \
                    mma16816(acc[mi][ni], ah[mi], &blf[ni >> 1][(ni & 1) * 2]); \
                    mma16816(acc[mi][ni], al[mi], &bhf[ni >> 1][(ni & 1) * 2]); \
                } \
        } \
    }

// ---------------- fused QKV GEMM: writes bf16 hi/lo ------------------------
// Q block pre-scaled by 0.125*log2(e) so flash can use bare exp2.
__global__ __launch_bounds__(256, 1)
void gemm_qkv_kernel(const __nv_bfloat16* __restrict__ Ah,
                     const __nv_bfloat16* __restrict__ Al,
                     const __nv_bfloat16* __restrict__ Bh,
                     const __nv_bfloat16* __restrict__ Bl,
                     const float* __restrict__ bq,
                     const float* __restrict__ bk,
                     const float* __restrict__ bv,
                     __nv_bfloat16* __restrict__ Ch,
                     __nv_bfloat16* __restrict__ Cl)
{
    extern __shared__ char smem[];
    const uint32_t sbase = smem_u32(smem);
    const int tid  = threadIdx.x;
    const int wid  = tid >> 5;
    const int lane = tid & 31;
    const int blockRow = blockIdx.y * 128;
    const int blockCol = blockIdx.x * 256;      // within one of Q/K/V
    const int wrow = (wid >> 2) * 64;
    const int wcol = (wid & 3) * 64;

    const float scale = (blockCol < DIM) ? 0.125f * 1.44269504088896f : 1.0f;
    const float* bsel;
    int cb;
    if (blockCol < DIM)            { bsel = bq; cb = blockCol; }
    else if (blockCol < 2 * DIM)   { bsel = bk; cb = blockCol - DIM; }
    else                           { bsel = bv; cb = blockCol - 2 * DIM; }

    float acc[4][8][4];
    #pragma unroll
    for (int mi = 0; mi < 4; mi++)
        #pragma unroll
        for (int ni = 0; ni < 8; ni++)
            #pragma unroll
            for (int j = 0; j < 4; j++) acc[mi][ni][j] = 0.f;

    const int aRow = wrow + (lane & 15);
    const int aCol = (lane >> 4) * 8;
    const int bRow = wcol + (lane >> 4) * 8 + (lane & 7);
    const int bCol = ((lane >> 3) & 1) * 8;

    GEMM_MAINLOOP();

    #pragma unroll
    for (int mi = 0; mi < 4; mi++) {
        const int r0 = blockRow + wrow + mi * 16 + (lane >> 2);
        #pragma unroll
        for (int ni = 0; ni < 8; ni++) {
            const int cc = wcol + ni * 8 + 2 * (lane & 3);
            float2 bv2 = *(const float2*)(bsel + cb + cc);
            const int gc = blockCol + cc;
            float v0x = (acc[mi][ni][0] + bv2.x) * scale;
            float v0y = (acc[mi][ni][1] + bv2.y) * scale;
            float v1x = (acc[mi][ni][2] + bv2.x) * scale;
            float v1y = (acc[mi][ni][3] + bv2.y) * scale;
            uint32_t h0, l0, h1, l1;
            split_pack(v0x, v0y, h0, l0);
            split_pack(v1x, v1y, h1, l1);
            *(uint32_t*)(Ch + (size_t)r0 * NQKV + gc)       = h0;
            *(uint32_t*)(Cl + (size_t)r0 * NQKV + gc)       = l0;
            *(uint32_t*)(Ch + (size_t)(r0 + 8) * NQKV + gc) = h1;
            *(uint32_t*)(Cl + (size_t)(r0 + 8) * NQKV + gc) = l1;
        }
    }
}

// ---------------- O-projection GEMM: fp32 out + bias -----------------------
__global__ __launch_bounds__(256, 1)
void gemm_mma_kernel(const __nv_bfloat16* __restrict__ Ah,
                     const __nv_bfloat16* __restrict__ Al,
                     const __nv_bfloat16* __restrict__ Bh,
                     const __nv_bfloat16* __restrict__ Bl,
                     const float* __restrict__ bias, float* __restrict__ C)
{
    extern __shared__ char smem[];
    const uint32_t sbase = smem_u32(smem);
    const int tid  = threadIdx.x;
    const int wid  = tid >> 5;
    const int lane = tid & 31;
    const int blockRow = blockIdx.y * 128;
    const int blockCol = blockIdx.x * 256;
    const int wrow = (wid >> 2) * 64;
    const int wcol = (wid & 3) * 64;

    float acc[4][8][4];
    #pragma unroll
    for (int mi = 0; mi < 4; mi++)
        #pragma unroll
        for (int ni = 0; ni < 8; ni++)
            #pragma unroll
            for (int j = 0; j < 4; j++) acc[mi][ni][j] = 0.f;

    const int aRow = wrow + (lane & 15);
    const int aCol = (lane >> 4) * 8;
    const int bRow = wcol + (lane >> 4) * 8 + (lane & 7);
    const int bCol = ((lane >> 3) & 1) * 8;

    GEMM_MAINLOOP();

    #pragma unroll
    for (int mi = 0; mi < 4; mi++) {
        const int r0 = blockRow + wrow + mi * 16 + (lane >> 2);
        #pragma unroll
        for (int ni = 0; ni < 8; ni++) {
            const int c0 = blockCol + wcol + ni * 8 + 2 * (lane & 3);
            float2 bv = *(const float2*)(bias + c0);
            float2 v0 = { acc[mi][ni][0] + bv.x, acc[mi][ni][1] + bv.y };
            float2 v1 = { acc[mi][ni][2] + bv.x, acc[mi][ni][3] + bv.y };
            *(float2*)(C + (size_t)r0 * DIM + c0)       = v0;
            *(float2*)(C + (size_t)(r0 + 8) * DIM + c0) = v1;
        }
    }
}

// ---------------- Flash attention (bf16-split mma, causal, softmax-one) ----
// Scores arrive pre-scaled by log2(e): softmax runs in the log2 domain with
// bare ex2.approx MUFU ops (identical math; exp2(-inf)=0). Online-max exact;
// 3-product S and PV; paired q-tiles; single-sync KV pipeline.
#define FQS 72
#define FQ_ELE   (128 * FQS)
#define FKV_ELE  (64 * FQS)
#define FKVBUF   (4 * FKV_ELE)
#define FLASH_SMEM ((2 * FQ_ELE + 2 * FKVBUF) * 2)   // 110592 bytes

__global__ __launch_bounds__(128, 2) void flash_mma_kernel(
    const __nv_bfloat16* __restrict__ QKVh,
    const __nv_bfloat16* __restrict__ QKVl,
    __nv_bfloat16* __restrict__ Ch,
    __nv_bfloat16* __restrict__ Cl)
{
    const int bx   = blockIdx.x;          // 0..7
    const int bh   = blockIdx.y;          // 0..31
    const int b    = bh >> 4;
    const int h    = bh & 15;
    const int tid  = threadIdx.x;
    const int wid  = tid >> 5;
    const int lane = tid & 31;
    const int wrow = wid * 32;
    const size_t rowbase = (size_t)b * SEQ;
    const int qcol = h * HD;
    const int kcol = qcol + DIM;
    const int vcol = qcol + 2 * DIM;

    extern __shared__ __nv_bfloat16 fsm[];
    const uint32_t uQh = smem_u32(fsm);
    const uint32_t uQl = uQh + FQ_ELE * 2;
    const uint32_t uKV0 = uQl + FQ_ELE * 2;
    #define KV_KH(bb) (uKV0 + (bb) * FKVBUF * 2)
    #define KV_KL(bb) (KV_KH(bb) + FKV_ELE * 2)
    #define KV_VH(bb) (KV_KH(bb) + 2 * FKV_ELE * 2)
    #define KV_VL(bb) (KV_KH(bb) + 3 * FKV_ELE * 2)

    #define ISSUE_Q(qb) { \
        _Pragma("unroll") \
        for (int i = 0; i < 8; i++) { \
            int idx = tid + i * 128; \
            int r = idx >> 3, seg = idx & 7; \
            size_t g = (rowbase + (qb) + r) * NQKV + qcol + seg * 8; \
            cp_async16(uQh + r * 144 + seg * 16, QKVh + g); \
            cp_async16(uQl + r * 144 + seg * 16, QKVl + g); \
        } }

    #define ISSUE_KV(kb, bb) { \
        _Pragma("unroll") \
        for (int i = 0; i < 4; i++) { \
            int idx = tid + i * 128; \
            int r = idx >> 3, seg = idx & 7; \
            size_t gk = (rowbase + (kb) + r) * NQKV + kcol + seg * 8; \
            size_t gv = (rowbase + (kb) + r) * NQKV + vcol + seg * 8; \
            uint32_t so = r * 144 + seg * 16; \
            cp_async16(KV_KH(bb) + so, QKVh + gk); \
            cp_async16(KV_KL(bb) + so, QKVl + gk); \
            cp_async16(KV_VH(bb) + so, QKVh + gv); \
            cp_async16(KV_VL(bb) + so, QKVl + gv); \
        } }

    for (int t = 0; t < 2; t++) {
        const int qt = (t == 0) ? bx : (15 - bx);
        const int qbase = qt * 128;

        float sa[2][8][4];
        float oa[2][8][4];
        float m[4], l[4];
        #pragma unroll
        for (int mi = 0; mi < 2; mi++)
            #pragma unroll
            for (int ni = 0; ni < 8; ni++)
                #pragma unroll
                for (int j = 0; j < 4; j++) oa[mi][ni][j] = 0.f;
        #pragma unroll
        for (int i = 0; i < 4; i++) { m[i] = -INFINITY; l[i] = 0.f; }

        __syncthreads();          // prior tile's smem readers done
        ISSUE_Q(qbase);
        ISSUE_KV(0, 0);
        cp_commit();

        const int nkt = 2 * qt + 2;
        for (int kt = 0; kt < nkt; kt++) {
            const int kbase = kt * 64;
            cp_wait<0>();
            __syncthreads();
            if (kt + 1 < nkt) { ISSUE_KV((kt + 1) * 64, (kt + 1) & 1); cp_commit(); }

            const int bb = kt & 1;
            const uint32_t uKh = KV_KH(bb), uKl = KV_KL(bb);
            const uint32_t uVh = KV_VH(bb), uVl = KV_VL(bb);

            #pragma unroll
            for (int mi = 0; mi < 2; mi++)
                #pragma unroll
                for (int ni = 0; ni < 8; ni++)
                    #pragma unroll
                    for (int j = 0; j < 4; j++) sa[mi][ni][j] = 0.f;

            // ---- S = Q @ K^T (3-product split) ----
            #pragma unroll
            for (int kk = 0; kk < 4; kk++) {
                uint32_t aqh[2][4], aql[2][4];
                #pragma unroll
                for (int mi = 0; mi < 2; mi++) {
                    uint32_t ao = ((wrow + mi * 16 + (lane & 15)) * FQS +
                                   kk * 16 + (lane >> 4) * 8) * 2;
                    ldsm4(aqh[mi], uQh + ao);
                    ldsm4(aql[mi], uQl + ao);
                }
                #pragma unroll
                for (int g = 0; g < 4; g++) {
                    uint32_t bh_[4], bl_[4];
                    uint32_t bo = ((g * 16 + (lane >> 4) * 8 + (lane & 7)) * FQS +
                                   kk * 16 + ((lane >> 3) & 1) * 8) * 2;
                    ldsm4(bh_, uKh + bo);
                    ldsm4(bl_, uKl + bo);
                    #pragma unroll
                    for (int mi = 0; mi < 2; mi++)
                        #pragma unroll
                        for (int p = 0; p < 2; p++) {
                            int ni = g * 2 + p;
                            mma16816(sa[mi][ni], aqh[mi], &bh_[p * 2]);
                            mma16816(sa[mi][ni], aqh[mi], &bl_[p * 2]);
                            mma16816(sa[mi][ni], aql[mi], &bh_[p * 2]);
                        }
                }
            }

            // ---- causal mask (near-diagonal tiles only) ----
            if (kbase + 63 > qbase + wrow) {
                #pragma unroll
                for (int mi = 0; mi < 2; mi++)
                    #pragma unroll
                    for (int ni = 0; ni < 8; ni++)
                        #pragma unroll
                        for (int j = 0; j < 4; j++) {
                            int qrow = qbase + wrow + mi * 16 + (lane >> 2) + (j >> 1) * 8;
                            int kc = kbase + ni * 8 + 2 * (lane & 3) + (j & 1);
                            if (kc > qrow) sa[mi][ni][j] = -INFINITY;
                        }
            }

            // ---- online softmax-one update (log2 domain, exact row max) ----
            #pragma unroll
            for (int mi = 0; mi < 2; mi++)
                #pragma unroll
                for (int rh = 0; rh < 2; rh++) {
                    const int ri = mi * 2 + rh;
                    float rmax = -INFINITY;
                    #pragma unroll
                    for (int ni = 0; ni < 8; ni++)
                        rmax = fmaxf(rmax, fmaxf(sa[mi][ni][rh * 2], sa[mi][ni][rh * 2 + 1]));
                    rmax = fmaxf(rmax, __shfl_xor_sync(0xffffffffu, rmax, 1));
                    rmax = fmaxf(rmax, __shfl_xor_sync(0xffffffffu, rmax, 2));
                    float mnew = fmaxf(m[ri], rmax);
                    float corr = ex2(m[ri] - mnew);
                    float sum = 0.f;
                    #pragma unroll
                    for (int ni = 0; ni < 8; ni++)
                        #pragma unroll
                        for (int j2 = 0; j2 < 2; j2++) {
                            float p = ex2(sa[mi][ni][rh * 2 + j2] - mnew);
                            sa[mi][ni][rh * 2 + j2] = p;
                            sum += p;
                        }
                    sum += __shfl_xor_sync(0xffffffffu, sum, 1);
                    sum += __shfl_xor_sync(0xffffffffu, sum, 2);
                    l[ri] = l[ri] * corr + sum;
                    m[ri] = mnew;
                    #pragma unroll
                    for (int ni = 0; ni < 8; ni++)
                        #pragma unroll
                        for (int j2 = 0; j2 < 2; j2++)
                            oa[mi][ni][rh * 2 + j2] *= corr;
                }

            // ---- O += P @ V (3-product split; trunc-based P split) ----
            #pragma unroll
            for (int kk = 0; kk < 4; kk++) {
                uint32_t ph[2][4], pl[2][4];
                #pragma unroll
                for (int mi = 0; mi < 2; mi++) {
                    split_pack_trunc(sa[mi][2 * kk][0],     sa[mi][2 * kk][1],     ph[mi][0], pl[mi][0]);
                    split_pack_trunc(sa[mi][2 * kk][2],     sa[mi][2 * kk][3],     ph[mi][1], pl[mi][1]);
                    split_pack_trunc(sa[mi][2 * kk + 1][0], sa[mi][2 * kk + 1][1], ph[mi][2], pl[mi][2]);
                    split_pack_trunc(sa[mi][2 * kk + 1][2], sa[mi][2 * kk + 1][3], ph[mi][3], pl[mi][3]);
                }
                #pragma unroll
                for (int dg = 0; dg < 4; dg++) {
                    uint32_t bvh[4], bvl[4];
                    uint32_t bo = ((kk * 16 + ((lane >> 3) & 1) * 8 + (lane & 7)) * FQS +
                                   dg * 16 + (lane >> 4) * 8) * 2;
                    ldsm4t(bvh, uVh + bo);
                    ldsm4t(bvl, uVl + bo);
                    #pragma unroll
                    for (int mi = 0; mi < 2; mi++)
                        #pragma unroll
                        for (int p = 0; p < 2; p++) {
                            int ni = dg * 2 + p;
                            mma16816(oa[mi][ni], ph[mi], &bvh[p * 2]);
                            mma16816(oa[mi][ni], ph[mi], &bvl[p * 2]);
                            mma16816(oa[mi][ni], pl[mi], &bvh[p * 2]);
                        }
                }
            }
        }

        // ---- epilogue: divide by (1 + l), write ctx bf16 hi/lo ----
        #pragma unroll
        for (int mi = 0; mi < 2; mi++) {
            const float inv0 = 1.f / (1.f + l[mi * 2 + 0]);
            const float inv1 = 1.f / (1.f + l[mi * 2 + 1]);
            const int r0 = qbase + wrow + mi * 16 + (lane >> 2);
            #pragma unroll
            for (int ni = 0; ni < 8; ni++) {
                const int c0 = ni * 8 + 2 * (lane & 3);
                uint32_t h0, l0, h1, l1;
                split_pack(oa[mi][ni][0] * inv0, oa[mi][ni][1] * inv0, h0, l0);
                split_pack(oa[mi][ni][2] * inv1, oa[mi][ni][3] * inv1, h1, l1);
                size_t o0 = (rowbase + r0) * DIM + qcol + c0;
                size_t o1 = (rowbase + r0 + 8) * DIM + qcol + c0;
                *(uint32_t*)(Ch + o0) = h0;
                *(uint32_t*)(Cl + o0) = l0;
                *(uint32_t*)(Ch + o1) = h1;
                *(uint32_t*)(Cl + o1) = l1;
            }
        }
    }
}

// ---------------- launcher -------------------------------------------------
extern "C" void kernel_launch(void* const* d_in, const int* in_sizes, int n_in,
                              void* d_out, int out_size)
{
    const float* x  = (const float*)d_in[0];
    const float* Wq = (const float*)d_in[1];
    const float* bq = (const float*)d_in[2];
    const float* Wk = (const float*)d_in[3];
    const float* bk = (const float*)d_in[4];
    const float* Wv = (const float*)d_in[5];
    const float* bv = (const float*)d_in[6];
    const float* Wo = (const float*)d_in[7];
    const float* bo = (const float*)d_in[8];
    float* out = (float*)d_out;

    __nv_bfloat16 *xh, *xl, *wth, *wtl, *qkvh, *qkvl;
    cudaGetSymbolAddress((void**)&xh,   g_xh);
    cudaGetSymbolAddress((void**)&xl,   g_xl);
    cudaGetSymbolAddress((void**)&wth,  g_wth);
    cudaGetSymbolAddress((void**)&wtl,  g_wtl);
    cudaGetSymbolAddress((void**)&qkvh, g_qkvh);
    cudaGetSymbolAddress((void**)&qkvl, g_qkvl);

    cudaFuncSetAttribute(flash_mma_kernel,
                         cudaFuncAttributeMaxDynamicSharedMemorySize, FLASH_SMEM);
    cudaFuncSetAttribute(gemm_qkv_kernel,
                         cudaFuncAttributeMaxDynamicSharedMemorySize, GEMM_SMEM);
    cudaFuncSetAttribute(gemm_mma_kernel,
                         cudaFuncAttributeMaxDynamicSharedMemorySize, GEMM_SMEM);

    const int n4 = MROWS * DIM / 4;

    split_kernel<<<(n4 + 255) / 256, 256>>>((const float4*)x, xh, xl, n4);
    dim3 tg(32, 32, 4);
    transpose_split4_kernel<<<tg, 256>>>(Wq, Wk, Wv, Wo, wth, wtl);

    dim3 gqkv(NQKV / 256, MROWS / 128);        // (12, 32)
    gemm_qkv_kernel<<<gqkv, 256, GEMM_SMEM>>>(xh, xl, wth, wtl, bq, bk, bv, qkvh, qkvl);

    dim3 attnGrid(SEQ / 256, BATCH * NHEAD);   // (8, 32): paired q-tiles
    flash_mma_kernel<<<attnGrid, 128, FLASH_SMEM>>>(qkvh, qkvl, xh, xl);

    dim3 go(DIM / 256, MROWS / 128);           // (4, 32)
    gemm_mma_kernel<<<go, 256, GEMM_SMEM>>>(xh, xl, wth + 3 * DIM * DIM, wtl + 3 * DIM * DIM, bo, out);
}